// round 13
// baseline (speedup 1.0000x reference)
#include <cuda_runtime.h>
#include <cuda_bf16.h>
#include <cuda_fp16.h>
#include <cstdint>

#define N_NODES 100000
#define N_EDGES 1600000
#define CH 128          // IN_CH = HEADS*HID = OUT_CH = 128
#define HEADS 4
#define HID 32
#define NEG_SLOPE 0.2f
#define NBLK 148
#define CBS 1024

// ---------------- scratch (static device globals; no allocation) ----------------
__device__ float g_h[(size_t)N_NODES * CH];       // x @ W, fp32 (51.2 MB)
__device__ float g_accum[(size_t)N_NODES * CH];   // normalized messages (51.2 MB)
__device__ float g_asrc[(size_t)N_NODES * HEADS]; // pre-scaled by log2(e)
__device__ float g_adst[(size_t)N_NODES * HEADS]; // pre-scaled by log2(e)
__device__ int   g_deg[N_NODES];
__device__ int   g_off[N_NODES];
__device__ int   g_pos[N_EDGES];                  // per-edge slot within its dst list
__device__ int   g_srcs[N_EDGES];
__device__ int   g_bsum[NBLK];
__device__ unsigned g_c[8];                        // grid-barrier counters (zero-init)
// pre-swizzled bf16 hi/lo images of W^T and lin_w^T ([n][k] layout, 32KB each)
__device__ __align__(16) unsigned char g_whi[32768];
__device__ __align__(16) unsigned char g_wlo[32768];
__device__ __align__(16) unsigned char g_lwhi[32768];
__device__ __align__(16) unsigned char g_lwlo[32768];

#define LOG2E 1.4426950408889634f

// ---------------- helpers ----------------
__device__ __forceinline__ uint32_t s2u(const void* p) {
    uint32_t a;
    asm("{ .reg .u64 t; cvta.to.shared.u64 t, %1; cvt.u32.u64 %0, t; }" : "=r"(a) : "l"(p));
    return a;
}

// swizzled byte offset inside a [rows][128 bf16] tile (256B rows, XOR-16B-chunk swizzle)
__device__ __forceinline__ uint32_t swz(int row, int col) {
    return (uint32_t)(row * 256 + ((((col >> 3) ^ (row & 7))) << 4) + (col & 7) * 2);
}

#define LDSM4(r, addr) \
    asm volatile("ldmatrix.sync.aligned.m8n8.x4.shared.b16 {%0,%1,%2,%3}, [%4];" \
        : "=r"((r)[0]), "=r"((r)[1]), "=r"((r)[2]), "=r"((r)[3]) : "r"(addr))

#define MMA16816(d, a, b0, b1) \
    asm volatile("mma.sync.aligned.m16n8k16.row.col.f32.bf16.bf16.f32 " \
        "{%0,%1,%2,%3}, {%4,%5,%6,%7}, {%8,%9}, {%0,%1,%2,%3};" \
        : "+f"((d)[0]), "+f"((d)[1]), "+f"((d)[2]), "+f"((d)[3]) \
        : "r"((a)[0]), "r"((a)[1]), "r"((a)[2]), "r"((a)[3]), "r"(b0), "r"(b1))

// fast 2^x and leaky-relu
__device__ __forceinline__ float ex2f(float x) {
    float r;
    asm("ex2.approx.f32 %0, %1;" : "=f"(r) : "f"(x));
    return r;
}
__device__ __forceinline__ float lrelu(float e) {
    return fmaf(fminf(e, 0.f), -(1.f - NEG_SLOPE), e);
}

// ---------------- software grid barrier ----------------
__device__ __forceinline__ void gbar(int ph) {
    __syncthreads();
    if (threadIdx.x == 0) {
        __threadfence();
        atomicAdd(&g_c[ph], 1u);
        while (*(volatile unsigned*)&g_c[ph] < (unsigned)NBLK) { __nanosleep(64); }
        __threadfence();
    }
    __syncthreads();
}

// ---------------- fused CSR build (pos-recording; atomic-free placement) ----------------
__global__ void __launch_bounds__(CBS, 1) csr_build(const int* __restrict__ ei, int E, int N)
{
    __shared__ int sm[CBS];
    const int b = blockIdx.x, t = threadIdx.x;
    const int gt = b * CBS + t;
    const int GS = NBLK * CBS;
    const int CHUNK = (N + NBLK - 1) / NBLK;
    const int base = b * CHUNK;

    for (int i = gt; i < N; i += GS) g_deg[i] = 0;
    gbar(0);

    for (int i = gt; i < E; i += GS) {
        int pos = atomicAdd(&g_deg[ei[E + i]], 1);
        g_pos[i] = pos;
    }
    gbar(1);

    int myv = 0;
    if (t < CHUNK && base + t < N) myv = __ldcg(&g_deg[base + t]);
    sm[t] = myv;
    __syncthreads();
#pragma unroll
    for (int d = 1; d < CBS; d <<= 1) {
        int v2 = (t >= d) ? sm[t - d] : 0;
        __syncthreads();
        sm[t] += v2;
        __syncthreads();
    }
    int incl = sm[t];
    if (t < CHUNK && base + t < N) g_off[base + t] = incl - myv;
    if (t == CBS - 1) g_bsum[b] = incl;
    gbar(2);

    if (b == 0) {
        int v = (t < NBLK) ? __ldcg(&g_bsum[t]) : 0;
        sm[t] = v;
        __syncthreads();
#pragma unroll
        for (int d = 1; d < CBS; d <<= 1) {
            int v2 = (t >= d) ? sm[t - d] : 0;
            __syncthreads();
            sm[t] += v2;
            __syncthreads();
        }
        if (t < NBLK) g_bsum[t] = sm[t] - v;
    }
    gbar(3);

    {
        int boff = __ldcg(&g_bsum[b]);
        if (t < CHUNK && base + t < N)
            g_off[base + t] += boff;
    }
    gbar(4);

    for (int i = gt; i < E; i += GS) {
        int dst = ei[E + i];
        g_srcs[__ldcg(&g_off[dst]) + g_pos[i]] = ei[i];
    }
    gbar(5);

    if (b == 0 && t < 8) g_c[t] = 0;
}

// ---------------- prep: W^T and lin_w^T -> bf16 hi/lo, swizzled (one launch) ----------------
__global__ void prep_all(const float* __restrict__ W, const float* __restrict__ LW) {
    int idx = blockIdx.x * blockDim.x + threadIdx.x;   // 32768
    int m   = idx >> 14;
    int rem = idx & 16383;
    int n = rem >> 7, k = rem & 127;
    const float* src = m ? LW : W;
    unsigned char* dhi = m ? g_lwhi : g_whi;
    unsigned char* dlo = m ? g_lwlo : g_wlo;
    float v = src[k * CH + n];
    __nv_bfloat16 h = __float2bfloat16(v);
    __nv_bfloat16 l = __float2bfloat16(v - __bfloat162float(h));
    uint32_t o = swz(n, k);
    *reinterpret_cast<__nv_bfloat16*>(dhi + o) = h;
    *reinterpret_cast<__nv_bfloat16*>(dlo + o) = l;
}

// ---------------- tensor-core GEMM (split-bf16 3-product), PERSISTENT blocks ----------------
// MODE 0: gemm1 -> C = g_h (fp32) + fused a_src/a_dst epilogue (v0=att_s, v1=att_d)
// MODE 1: gemm2 -> C = out (fp32) with bias(v0) + ReLU
template<int MODE>
__global__ void __launch_bounds__(256, 2) gemm_mma(
    const float* __restrict__ A,
    const unsigned char* __restrict__ Bhi_g, const unsigned char* __restrict__ Blo_g,
    const float* __restrict__ v0, const float* __restrict__ v1,
    float* __restrict__ C, int M)
{
    extern __shared__ __align__(16) unsigned char smem[];
    // layout: A_hi 16K | A_lo 16K | B_hi 32K | B_lo 32K
    const uint32_t sb = s2u(smem);
    const int tid = threadIdx.x, lane = tid & 31, w = tid >> 5;

    // copy B tiles once
    {
        const int4* bh = reinterpret_cast<const int4*>(Bhi_g);
        const int4* bl = reinterpret_cast<const int4*>(Blo_g);
        int4* dh = reinterpret_cast<int4*>(smem + 32768);
        int4* dl = reinterpret_cast<int4*>(smem + 65536);
#pragma unroll
        for (int u = 0; u < 8; ++u) {
            int f = tid + u * 256;
            dh[f] = bh[f];
            dl[f] = bl[f];
        }
    }

    const int wr = (w >> 1) * 16;
    const int wc = (w & 1) * 64;
    const int arow  = wr + (lane & 7) + ((lane >> 3) & 1) * 8;
    const int asel  = lane >> 4;
    const int arow7 = arow & 7;
    const int bg_row = (lane & 7) + ((lane >> 4) & 1) * 8;
    const int bsel   = (lane >> 3) & 1;

    const int ntiles = (M + 63) / 64;
    for (int tile = blockIdx.x; tile < ntiles; tile += gridDim.x) {
        const int row0 = tile * 64;

        __syncthreads();   // protect A smem from previous iteration's readers

        // stage A tile: fp32 -> bf16 hi/lo, swizzled
#pragma unroll
        for (int u = 0; u < 8; ++u) {
            int f = tid + u * 256;
            int r = f >> 5;
            int c = (f & 31) * 4;
            float4 v = make_float4(0.f, 0.f, 0.f, 0.f);
            if (row0 + r < M)
                v = *reinterpret_cast<const float4*>(&A[(size_t)(row0 + r) * CH + c]);
            __nv_bfloat162 h01 = __floats2bfloat162_rn(v.x, v.y);
            __nv_bfloat162 h23 = __floats2bfloat162_rn(v.z, v.w);
            __nv_bfloat162 lo01 = __floats2bfloat162_rn(v.x - __bfloat162float(h01.x),
                                                        v.y - __bfloat162float(h01.y));
            __nv_bfloat162 lo23 = __floats2bfloat162_rn(v.z - __bfloat162float(h23.x),
                                                        v.w - __bfloat162float(h23.y));
            uint32_t o = swz(r, c);
            uint2 uh, ul;
            uh.x = *reinterpret_cast<uint32_t*>(&h01);
            uh.y = *reinterpret_cast<uint32_t*>(&h23);
            ul.x = *reinterpret_cast<uint32_t*>(&lo01);
            ul.y = *reinterpret_cast<uint32_t*>(&lo23);
            *reinterpret_cast<uint2*>(smem + o)         = uh;
            *reinterpret_cast<uint2*>(smem + 16384 + o) = ul;
        }
        __syncthreads();

        float acc[8][4];
#pragma unroll
        for (int j = 0; j < 8; ++j)
#pragma unroll
            for (int q = 0; q < 4; ++q) acc[j][q] = 0.f;

#pragma unroll
        for (int kk = 0; kk < 8; ++kk) {
            uint32_t a_hi[4], a_lo[4];
            uint32_t aaddr = sb + (uint32_t)(arow * 256) +
                             (uint32_t)((((kk * 2 + asel) ^ arow7)) << 4);
            LDSM4(a_hi, aaddr);
            LDSM4(a_lo, aaddr + 16384);

            uint32_t b_hi[16], b_lo[16];
#pragma unroll
            for (int g = 0; g < 4; ++g) {
                int brow = wc + g * 16 + bg_row;
                uint32_t baddr = sb + 32768 + (uint32_t)(brow * 256) +
                                 (uint32_t)((((kk * 2 + bsel) ^ (brow & 7))) << 4);
                LDSM4(&b_hi[g * 4], baddr);
                LDSM4(&b_lo[g * 4], baddr + 32768);
            }

#pragma unroll
            for (int j = 0; j < 8; ++j) {
                int i0 = (j >> 1) * 4 + (j & 1) * 2;
                MMA16816(acc[j], a_hi, b_hi[i0], b_hi[i0 + 1]);
            }
#pragma unroll
            for (int j = 0; j < 8; ++j) {
                int i0 = (j >> 1) * 4 + (j & 1) * 2;
                MMA16816(acc[j], a_hi, b_lo[i0], b_lo[i0 + 1]);
            }
#pragma unroll
            for (int j = 0; j < 8; ++j) {
                int i0 = (j >> 1) * 4 + (j & 1) * 2;
                MMA16816(acc[j], a_lo, b_hi[i0], b_hi[i0 + 1]);
            }
        }

        const int r_g = row0 + wr + (lane >> 2);
#pragma unroll
        for (int j = 0; j < 8; ++j) {
            int n0 = wc + j * 8 + (lane & 3) * 2;
            float2 o0 = make_float2(acc[j][0], acc[j][1]);
            float2 o1 = make_float2(acc[j][2], acc[j][3]);
            if (MODE == 1) {
                float b0 = __ldg(&v0[n0]), b1 = __ldg(&v0[n0 + 1]);
                o0.x = fmaxf(o0.x + b0, 0.f); o0.y = fmaxf(o0.y + b1, 0.f);
                o1.x = fmaxf(o1.x + b0, 0.f); o1.y = fmaxf(o1.y + b1, 0.f);
            }
            if (r_g < M)
                *reinterpret_cast<float2*>(&C[(size_t)r_g * CH + n0]) = o0;
            if (r_g + 8 < M)
                *reinterpret_cast<float2*>(&C[(size_t)(r_g + 8) * CH + n0]) = o1;
        }

        if (MODE == 0) {
            // fused att projections, pre-scaled by log2(e)
            float ps[2][2] = {{0.f, 0.f}, {0.f, 0.f}};
            float pd[2][2] = {{0.f, 0.f}, {0.f, 0.f}};
#pragma unroll
            for (int j = 0; j < 8; ++j) {
                int n0 = wc + j * 8 + (lane & 3) * 2;
                float s0 = __ldg(&v0[n0]), s1 = __ldg(&v0[n0 + 1]);
                float d0 = __ldg(&v1[n0]), d1 = __ldg(&v1[n0 + 1]);
                int hh = j >> 2;
                ps[hh][0] += acc[j][0] * s0 + acc[j][1] * s1;
                ps[hh][1] += acc[j][2] * s0 + acc[j][3] * s1;
                pd[hh][0] += acc[j][0] * d0 + acc[j][1] * d1;
                pd[hh][1] += acc[j][2] * d0 + acc[j][3] * d1;
            }
#pragma unroll
            for (int o = 1; o < 4; o <<= 1) {
#pragma unroll
                for (int hh = 0; hh < 2; ++hh)
#pragma unroll
                    for (int rh = 0; rh < 2; ++rh) {
                        ps[hh][rh] += __shfl_xor_sync(0xFFFFFFFFu, ps[hh][rh], o);
                        pd[hh][rh] += __shfl_xor_sync(0xFFFFFFFFu, pd[hh][rh], o);
                    }
            }
            if ((lane & 3) == 0) {
                int h0 = wc >> 5;
                if (r_g < M) {
                    g_asrc[(size_t)r_g * HEADS + h0]     = ps[0][0] * LOG2E;
                    g_asrc[(size_t)r_g * HEADS + h0 + 1] = ps[1][0] * LOG2E;
                    g_adst[(size_t)r_g * HEADS + h0]     = pd[0][0] * LOG2E;
                    g_adst[(size_t)r_g * HEADS + h0 + 1] = pd[1][0] * LOG2E;
                }
                if (r_g + 8 < M) {
                    g_asrc[(size_t)(r_g + 8) * HEADS + h0]     = ps[0][1] * LOG2E;
                    g_asrc[(size_t)(r_g + 8) * HEADS + h0 + 1] = ps[1][1] * LOG2E;
                    g_adst[(size_t)(r_g + 8) * HEADS + h0]     = pd[0][1] * LOG2E;
                    g_adst[(size_t)(r_g + 8) * HEADS + h0 + 1] = pd[1][1] * LOG2E;
                }
            }
        }
    }
}

// ---------------- gather v3: fp32 h, 2 edges/step, 8 ch/lane, peeled tail ----------------
__global__ void __launch_bounds__(256) gather_kernel(int N)
{
    int node = (blockIdx.x * blockDim.x + threadIdx.x) >> 5;
    if (node >= N) return;
    const int lane = threadIdx.x & 31;
    const int sub  = lane & 15;        // channel group
    const int half = lane >> 4;        // edge parity within a step pair
    const int head = sub >> 2;
    const int chan = sub * 8;

    const int off = g_off[node];
    const int deg = g_deg[node];

    const float ad_my = __ldg(&g_adst[(size_t)node * HEADS + head]);

    float acc[8];
#pragma unroll
    for (int c = 0; c < 8; ++c) acc[c] = 0.f;
    float s_my = 0.f;

    const int nfull = deg & ~31;

    // full 32-edge chunks: no bounds checks
    for (int base = 0; base < nfull; base += 32) {
        int idx = g_srcs[off + base + lane];
#pragma unroll
        for (int j = 0; j < 32; j += 4) {
            int s0 = __shfl_sync(0xFFFFFFFFu, idx, j + half);
            int s1 = __shfl_sync(0xFFFFFFFFu, idx, j + 2 + half);
            float as0 = __ldg(&g_asrc[(size_t)s0 * HEADS + head]);
            float as1 = __ldg(&g_asrc[(size_t)s1 * HEADS + head]);
            const float* h0p = &g_h[(size_t)s0 * CH + chan];
            const float* h1p = &g_h[(size_t)s1 * CH + chan];
            float4 a4 = *reinterpret_cast<const float4*>(h0p);
            float4 b4 = *reinterpret_cast<const float4*>(h0p + 4);
            float4 c4 = *reinterpret_cast<const float4*>(h1p);
            float4 d4 = *reinterpret_cast<const float4*>(h1p + 4);

            float x0 = ex2f(lrelu(as0 + ad_my));
            float x1 = ex2f(lrelu(as1 + ad_my));

            acc[0] = fmaf(x0, a4.x, acc[0]); acc[1] = fmaf(x0, a4.y, acc[1]);
            acc[2] = fmaf(x0, a4.z, acc[2]); acc[3] = fmaf(x0, a4.w, acc[3]);
            acc[4] = fmaf(x0, b4.x, acc[4]); acc[5] = fmaf(x0, b4.y, acc[5]);
            acc[6] = fmaf(x0, b4.z, acc[6]); acc[7] = fmaf(x0, b4.w, acc[7]);
            acc[0] = fmaf(x1, c4.x, acc[0]); acc[1] = fmaf(x1, c4.y, acc[1]);
            acc[2] = fmaf(x1, c4.z, acc[2]); acc[3] = fmaf(x1, c4.w, acc[3]);
            acc[4] = fmaf(x1, d4.x, acc[4]); acc[5] = fmaf(x1, d4.y, acc[5]);
            acc[6] = fmaf(x1, d4.z, acc[6]); acc[7] = fmaf(x1, d4.w, acc[7]);
            s_my += x0 + x1;
        }
    }

    // partial tail chunk
    if (nfull < deg) {
        int idx = 0;
        if (nfull + lane < deg) idx = g_srcs[off + nfull + lane];
        const int cnt = deg - nfull;
        for (int j = 0; j < cnt; j += 4) {
            int e0 = j + half;
            int e1 = j + 2 + half;
            int s0 = __shfl_sync(0xFFFFFFFFu, idx, e0);
            int s1 = __shfl_sync(0xFFFFFFFFu, idx, e1);
            float as0 = __ldg(&g_asrc[(size_t)s0 * HEADS + head]);
            float as1 = __ldg(&g_asrc[(size_t)s1 * HEADS + head]);
            const float* h0p = &g_h[(size_t)s0 * CH + chan];
            const float* h1p = &g_h[(size_t)s1 * CH + chan];
            float4 a4 = *reinterpret_cast<const float4*>(h0p);
            float4 b4 = *reinterpret_cast<const float4*>(h0p + 4);
            float4 c4 = *reinterpret_cast<const float4*>(h1p);
            float4 d4 = *reinterpret_cast<const float4*>(h1p + 4);

            float x0 = (e0 < cnt) ? ex2f(lrelu(as0 + ad_my)) : 0.f;
            float x1 = (e1 < cnt) ? ex2f(lrelu(as1 + ad_my)) : 0.f;

            acc[0] = fmaf(x0, a4.x, acc[0]); acc[1] = fmaf(x0, a4.y, acc[1]);
            acc[2] = fmaf(x0, a4.z, acc[2]); acc[3] = fmaf(x0, a4.w, acc[3]);
            acc[4] = fmaf(x0, b4.x, acc[4]); acc[5] = fmaf(x0, b4.y, acc[5]);
            acc[6] = fmaf(x0, b4.z, acc[6]); acc[7] = fmaf(x0, b4.w, acc[7]);
            acc[0] = fmaf(x1, c4.x, acc[0]); acc[1] = fmaf(x1, c4.y, acc[1]);
            acc[2] = fmaf(x1, c4.z, acc[2]); acc[3] = fmaf(x1, c4.w, acc[3]);
            acc[4] = fmaf(x1, d4.x, acc[4]); acc[5] = fmaf(x1, d4.y, acc[5]);
            acc[6] = fmaf(x1, d4.z, acc[6]); acc[7] = fmaf(x1, d4.w, acc[7]);
            s_my += x0 + x1;
        }
    }

#pragma unroll
    for (int c = 0; c < 8; ++c)
        acc[c] += __shfl_xor_sync(0xFFFFFFFFu, acc[c], 16);
    s_my += __shfl_xor_sync(0xFFFFFFFFu, s_my, 16);

    if (half == 0) {
        float inv = 1.f / (s_my + 1e-16f);
        float4 o0 = make_float4(acc[0] * inv, acc[1] * inv, acc[2] * inv, acc[3] * inv);
        float4 o1 = make_float4(acc[4] * inv, acc[5] * inv, acc[6] * inv, acc[7] * inv);
        float* dst = &g_accum[(size_t)node * CH + chan];
        *reinterpret_cast<float4*>(dst)     = o0;
        *reinterpret_cast<float4*>(dst + 4) = o1;
    }
}

// ---------------- launch ----------------
extern "C" void kernel_launch(void* const* d_in, const int* in_sizes, int n_in,
                              void* d_out, int out_size)
{
    const float* x     = (const float*)d_in[0];
    const int*   ei    = (const int*)  d_in[1];
    const float* W     = (const float*)d_in[2];
    const float* att_s = (const float*)d_in[3];
    const float* att_d = (const float*)d_in[4];
    const float* lin_w = (const float*)d_in[5];
    const float* lin_b = (const float*)d_in[6];
    float* out = (float*)d_out;

    int N = in_sizes[0] / CH;    // 100000
    int E = in_sizes[1] / 2;     // 1600000

    void *p_h, *p_acc, *p_whi, *p_wlo, *p_lwhi, *p_lwlo;
    cudaGetSymbolAddress(&p_h, g_h);
    cudaGetSymbolAddress(&p_acc, g_accum);
    cudaGetSymbolAddress(&p_whi, g_whi);
    cudaGetSymbolAddress(&p_wlo, g_wlo);
    cudaGetSymbolAddress(&p_lwhi, g_lwhi);
    cudaGetSymbolAddress(&p_lwlo, g_lwlo);

    const int SMEM = 98304;
    cudaFuncSetAttribute(gemm_mma<0>, cudaFuncAttributeMaxDynamicSharedMemorySize, SMEM);
    cudaFuncSetAttribute(gemm_mma<1>, cudaFuncAttributeMaxDynamicSharedMemorySize, SMEM);

    int ntiles = (N + 63) / 64;
    int gemm_blocks = (ntiles < 296) ? ntiles : 296;   // persistent, 2/SM

    // fork: csr_build (side stream) || prep + gemm1 (main stream) — proven topology
    cudaStream_t s2;
    cudaStreamCreateWithFlags(&s2, cudaStreamNonBlocking);
    cudaEvent_t ev_fork, ev_join;
    cudaEventCreateWithFlags(&ev_fork, cudaEventDisableTiming);
    cudaEventCreateWithFlags(&ev_join, cudaEventDisableTiming);

    cudaEventRecord(ev_fork, 0);
    cudaStreamWaitEvent(s2, ev_fork, 0);
    csr_build<<<NBLK, CBS, 0, s2>>>(ei, E, N);                                  // 0
    cudaEventRecord(ev_join, s2);

    prep_all<<<128, 256>>>(W, lin_w);                                           // 1
    gemm_mma<0><<<gemm_blocks, 256, SMEM>>>(                                    // 2
        x, (const unsigned char*)p_whi, (const unsigned char*)p_wlo,
        att_s, att_d, (float*)p_h, N);

    cudaStreamWaitEvent(0, ev_join, 0);
    gather_kernel<<<(N * 32 + 255) / 256, 256>>>(N);                            // 3 <- profiled
    gemm_mma<1><<<gemm_blocks, 256, SMEM>>>(                                    // 4
        (const float*)p_acc, (const unsigned char*)p_lwhi, (const unsigned char*)p_lwlo,
        lin_b, nullptr, out, N);
}

// round 14
// speedup vs baseline: 1.0368x; 1.0368x over previous
#include <cuda_runtime.h>
#include <cuda_bf16.h>
#include <cuda_fp16.h>
#include <cstdint>

#define N_NODES 100000
#define N_EDGES 1600000
#define CH 128          // IN_CH = HEADS*HID = OUT_CH = 128
#define HEADS 4
#define HID 32
#define NEG_SLOPE 0.2f
#define NBLK 148
#define CBS 1024

// ---------------- scratch (static device globals; no allocation) ----------------
__device__ __half g_h[(size_t)N_NODES * CH];      // x @ W, fp16 (25.6 MB)
__device__ __half g_accum[(size_t)N_NODES * CH];  // normalized messages, fp16 (25.6 MB)
__device__ float g_asrc[(size_t)N_NODES * HEADS]; // pre-scaled by log2(e)
__device__ float g_adst[(size_t)N_NODES * HEADS]; // pre-scaled by log2(e)
__device__ int   g_deg[N_NODES];
__device__ int   g_off[N_NODES];
__device__ int   g_pos[N_EDGES];                  // per-edge slot within its dst list
__device__ int   g_srcs[N_EDGES];
__device__ int   g_bsum[NBLK];
__device__ unsigned g_c[8];                        // grid-barrier counters (zero-init)
// pre-swizzled bf16 hi/lo images of W^T and lin_w^T ([n][k] layout, 32KB each)
__device__ __align__(16) unsigned char g_whi[32768];
__device__ __align__(16) unsigned char g_wlo[32768];
__device__ __align__(16) unsigned char g_lwhi[32768];
__device__ __align__(16) unsigned char g_lwlo[32768];

#define LOG2E 1.4426950408889634f

// ---------------- helpers ----------------
__device__ __forceinline__ uint32_t s2u(const void* p) {
    uint32_t a;
    asm("{ .reg .u64 t; cvta.to.shared.u64 t, %1; cvt.u32.u64 %0, t; }" : "=r"(a) : "l"(p));
    return a;
}

// swizzled byte offset inside a [rows][128 bf16] tile (256B rows, XOR-16B-chunk swizzle)
__device__ __forceinline__ uint32_t swz(int row, int col) {
    return (uint32_t)(row * 256 + ((((col >> 3) ^ (row & 7))) << 4) + (col & 7) * 2);
}

#define LDSM4(r, addr) \
    asm volatile("ldmatrix.sync.aligned.m8n8.x4.shared.b16 {%0,%1,%2,%3}, [%4];" \
        : "=r"((r)[0]), "=r"((r)[1]), "=r"((r)[2]), "=r"((r)[3]) : "r"(addr))

#define MMA16816(d, a, b0, b1) \
    asm volatile("mma.sync.aligned.m16n8k16.row.col.f32.bf16.bf16.f32 " \
        "{%0,%1,%2,%3}, {%4,%5,%6,%7}, {%8,%9}, {%0,%1,%2,%3};" \
        : "+f"((d)[0]), "+f"((d)[1]), "+f"((d)[2]), "+f"((d)[3]) \
        : "r"((a)[0]), "r"((a)[1]), "r"((a)[2]), "r"((a)[3]), "r"(b0), "r"(b1))

// fast 2^x and leaky-relu
__device__ __forceinline__ float ex2f(float x) {
    float r;
    asm("ex2.approx.f32 %0, %1;" : "=f"(r) : "f"(x));
    return r;
}
__device__ __forceinline__ float lrelu(float e) {
    return fmaf(fminf(e, 0.f), -(1.f - NEG_SLOPE), e);
}

// ---------------- software grid barrier ----------------
__device__ __forceinline__ void gbar(int ph) {
    __syncthreads();
    if (threadIdx.x == 0) {
        __threadfence();
        atomicAdd(&g_c[ph], 1u);
        while (*(volatile unsigned*)&g_c[ph] < (unsigned)NBLK) { __nanosleep(64); }
        __threadfence();
    }
    __syncthreads();
}

// ---------------- fused CSR build (pos-recording; atomic-free placement) ----------------
__global__ void __launch_bounds__(CBS, 1) csr_build(const int* __restrict__ ei, int E, int N)
{
    __shared__ int sm[CBS];
    const int b = blockIdx.x, t = threadIdx.x;
    const int gt = b * CBS + t;
    const int GS = NBLK * CBS;
    const int CHUNK = (N + NBLK - 1) / NBLK;
    const int base = b * CHUNK;

    for (int i = gt; i < N; i += GS) g_deg[i] = 0;
    gbar(0);

    for (int i = gt; i < E; i += GS) {
        int pos = atomicAdd(&g_deg[ei[E + i]], 1);
        g_pos[i] = pos;
    }
    gbar(1);

    int myv = 0;
    if (t < CHUNK && base + t < N) myv = __ldcg(&g_deg[base + t]);
    sm[t] = myv;
    __syncthreads();
#pragma unroll
    for (int d = 1; d < CBS; d <<= 1) {
        int v2 = (t >= d) ? sm[t - d] : 0;
        __syncthreads();
        sm[t] += v2;
        __syncthreads();
    }
    int incl = sm[t];
    if (t < CHUNK && base + t < N) g_off[base + t] = incl - myv;
    if (t == CBS - 1) g_bsum[b] = incl;
    gbar(2);

    if (b == 0) {
        int v = (t < NBLK) ? __ldcg(&g_bsum[t]) : 0;
        sm[t] = v;
        __syncthreads();
#pragma unroll
        for (int d = 1; d < CBS; d <<= 1) {
            int v2 = (t >= d) ? sm[t - d] : 0;
            __syncthreads();
            sm[t] += v2;
            __syncthreads();
        }
        if (t < NBLK) g_bsum[t] = sm[t] - v;
    }
    gbar(3);

    {
        int boff = __ldcg(&g_bsum[b]);
        if (t < CHUNK && base + t < N)
            g_off[base + t] += boff;
    }
    gbar(4);

    for (int i = gt; i < E; i += GS) {
        int dst = ei[E + i];
        g_srcs[__ldcg(&g_off[dst]) + g_pos[i]] = ei[i];
    }
    gbar(5);

    if (b == 0 && t < 8) g_c[t] = 0;
}

// ---------------- prep: W^T and lin_w^T -> bf16 hi/lo, swizzled (one launch) ----------------
__global__ void prep_all(const float* __restrict__ W, const float* __restrict__ LW) {
    int idx = blockIdx.x * blockDim.x + threadIdx.x;   // 32768
    int m   = idx >> 14;
    int rem = idx & 16383;
    int n = rem >> 7, k = rem & 127;
    const float* src = m ? LW : W;
    unsigned char* dhi = m ? g_lwhi : g_whi;
    unsigned char* dlo = m ? g_lwlo : g_wlo;
    float v = src[k * CH + n];
    __nv_bfloat16 h = __float2bfloat16(v);
    __nv_bfloat16 l = __float2bfloat16(v - __bfloat162float(h));
    uint32_t o = swz(n, k);
    *reinterpret_cast<__nv_bfloat16*>(dhi + o) = h;
    *reinterpret_cast<__nv_bfloat16*>(dlo + o) = l;
}

// ---------------- tensor-core GEMM (split-bf16 3-product), PERSISTENT blocks ----------------
// MODE 0: A = fp32 x;      C = g_h (fp16) + fused a_src/a_dst epilogue (v0=att_s, v1=att_d)
// MODE 1: A = fp16 accum;  C = out (fp32) with bias(v0) + ReLU
template<int MODE>
__global__ void __launch_bounds__(256, 2) gemm_mma(
    const void* __restrict__ Av,
    const unsigned char* __restrict__ Bhi_g, const unsigned char* __restrict__ Blo_g,
    const float* __restrict__ v0, const float* __restrict__ v1,
    void* __restrict__ Cv, int M)
{
    extern __shared__ __align__(16) unsigned char smem[];
    // layout: A_hi 16K | A_lo 16K | B_hi 32K | B_lo 32K
    const uint32_t sb = s2u(smem);
    const int tid = threadIdx.x, lane = tid & 31, w = tid >> 5;

    // copy B tiles once
    {
        const int4* bh = reinterpret_cast<const int4*>(Bhi_g);
        const int4* bl = reinterpret_cast<const int4*>(Blo_g);
        int4* dh = reinterpret_cast<int4*>(smem + 32768);
        int4* dl = reinterpret_cast<int4*>(smem + 65536);
#pragma unroll
        for (int u = 0; u < 8; ++u) {
            int f = tid + u * 256;
            dh[f] = bh[f];
            dl[f] = bl[f];
        }
    }

    const int wr = (w >> 1) * 16;
    const int wc = (w & 1) * 64;
    const int arow  = wr + (lane & 7) + ((lane >> 3) & 1) * 8;
    const int asel  = lane >> 4;
    const int arow7 = arow & 7;
    const int bg_row = (lane & 7) + ((lane >> 4) & 1) * 8;
    const int bsel   = (lane >> 3) & 1;

    const int ntiles = (M + 63) / 64;
    for (int tile = blockIdx.x; tile < ntiles; tile += gridDim.x) {
        const int row0 = tile * 64;

        __syncthreads();   // protect A smem from previous iteration's readers

        if (MODE == 0) {
            // A is fp32: 8 iters of float4
            const float* A = (const float*)Av;
#pragma unroll
            for (int u = 0; u < 8; ++u) {
                int f = tid + u * 256;
                int r = f >> 5;
                int c = (f & 31) * 4;
                float4 v = make_float4(0.f, 0.f, 0.f, 0.f);
                if (row0 + r < M)
                    v = *reinterpret_cast<const float4*>(&A[(size_t)(row0 + r) * CH + c]);
                __nv_bfloat162 h01 = __floats2bfloat162_rn(v.x, v.y);
                __nv_bfloat162 h23 = __floats2bfloat162_rn(v.z, v.w);
                __nv_bfloat162 lo01 = __floats2bfloat162_rn(v.x - __bfloat162float(h01.x),
                                                            v.y - __bfloat162float(h01.y));
                __nv_bfloat162 lo23 = __floats2bfloat162_rn(v.z - __bfloat162float(h23.x),
                                                            v.w - __bfloat162float(h23.y));
                uint32_t o = swz(r, c);
                uint2 uh, ul;
                uh.x = *reinterpret_cast<uint32_t*>(&h01);
                uh.y = *reinterpret_cast<uint32_t*>(&h23);
                ul.x = *reinterpret_cast<uint32_t*>(&lo01);
                ul.y = *reinterpret_cast<uint32_t*>(&lo23);
                *reinterpret_cast<uint2*>(smem + o)         = uh;
                *reinterpret_cast<uint2*>(smem + 16384 + o) = ul;
            }
        } else {
            // A is fp16: 4 iters of uint4 (8 halves); c aligned to 8 -> one 16B swizzle chunk
            const __half* A = (const __half*)Av;
#pragma unroll
            for (int u = 0; u < 4; ++u) {
                int f = tid + u * 256;          // [0, 1024)
                int r = f >> 4;
                int c = (f & 15) * 8;
                uint4 hv = make_uint4(0u, 0u, 0u, 0u);
                if (row0 + r < M)
                    hv = *reinterpret_cast<const uint4*>(&A[(size_t)(row0 + r) * CH + c]);
                const __half2* hp = reinterpret_cast<const __half2*>(&hv);
                uint32_t hi[4], lo[4];
#pragma unroll
                for (int q = 0; q < 4; ++q) {
                    float2 t = __half22float2(hp[q]);
                    __nv_bfloat162 bh = __floats2bfloat162_rn(t.x, t.y);
                    __nv_bfloat162 bl = __floats2bfloat162_rn(t.x - __bfloat162float(bh.x),
                                                              t.y - __bfloat162float(bh.y));
                    hi[q] = *reinterpret_cast<uint32_t*>(&bh);
                    lo[q] = *reinterpret_cast<uint32_t*>(&bl);
                }
                uint32_t o = swz(r, c);
                *reinterpret_cast<uint4*>(smem + o)         = make_uint4(hi[0], hi[1], hi[2], hi[3]);
                *reinterpret_cast<uint4*>(smem + 16384 + o) = make_uint4(lo[0], lo[1], lo[2], lo[3]);
            }
        }
        __syncthreads();

        float acc[8][4];
#pragma unroll
        for (int j = 0; j < 8; ++j)
#pragma unroll
            for (int q = 0; q < 4; ++q) acc[j][q] = 0.f;

#pragma unroll
        for (int kk = 0; kk < 8; ++kk) {
            uint32_t a_hi[4], a_lo[4];
            uint32_t aaddr = sb + (uint32_t)(arow * 256) +
                             (uint32_t)((((kk * 2 + asel) ^ arow7)) << 4);
            LDSM4(a_hi, aaddr);
            LDSM4(a_lo, aaddr + 16384);

            uint32_t b_hi[16], b_lo[16];
#pragma unroll
            for (int g = 0; g < 4; ++g) {
                int brow = wc + g * 16 + bg_row;
                uint32_t baddr = sb + 32768 + (uint32_t)(brow * 256) +
                                 (uint32_t)((((kk * 2 + bsel) ^ (brow & 7))) << 4);
                LDSM4(&b_hi[g * 4], baddr);
                LDSM4(&b_lo[g * 4], baddr + 32768);
            }

#pragma unroll
            for (int j = 0; j < 8; ++j) {
                int i0 = (j >> 1) * 4 + (j & 1) * 2;
                MMA16816(acc[j], a_hi, b_hi[i0], b_hi[i0 + 1]);
            }
#pragma unroll
            for (int j = 0; j < 8; ++j) {
                int i0 = (j >> 1) * 4 + (j & 1) * 2;
                MMA16816(acc[j], a_hi, b_lo[i0], b_lo[i0 + 1]);
            }
#pragma unroll
            for (int j = 0; j < 8; ++j) {
                int i0 = (j >> 1) * 4 + (j & 1) * 2;
                MMA16816(acc[j], a_lo, b_hi[i0], b_hi[i0 + 1]);
            }
        }

        const int r_g = row0 + wr + (lane >> 2);
#pragma unroll
        for (int j = 0; j < 8; ++j) {
            int n0 = wc + j * 8 + (lane & 3) * 2;
            if (MODE == 1) {
                float* C = (float*)Cv;
                float b0 = __ldg(&v0[n0]), b1 = __ldg(&v0[n0 + 1]);
                float2 o0, o1;
                o0.x = fmaxf(acc[j][0] + b0, 0.f); o0.y = fmaxf(acc[j][1] + b1, 0.f);
                o1.x = fmaxf(acc[j][2] + b0, 0.f); o1.y = fmaxf(acc[j][3] + b1, 0.f);
                if (r_g < M)
                    *reinterpret_cast<float2*>(&C[(size_t)r_g * CH + n0]) = o0;
                if (r_g + 8 < M)
                    *reinterpret_cast<float2*>(&C[(size_t)(r_g + 8) * CH + n0]) = o1;
            } else {
                __half* C = (__half*)Cv;
                __half2 o0 = __float22half2_rn(make_float2(acc[j][0], acc[j][1]));
                __half2 o1 = __float22half2_rn(make_float2(acc[j][2], acc[j][3]));
                if (r_g < M)
                    *reinterpret_cast<__half2*>(&C[(size_t)r_g * CH + n0]) = o0;
                if (r_g + 8 < M)
                    *reinterpret_cast<__half2*>(&C[(size_t)(r_g + 8) * CH + n0]) = o1;
            }
        }

        if (MODE == 0) {
            // fused att projections, pre-scaled by log2(e)
            float ps[2][2] = {{0.f, 0.f}, {0.f, 0.f}};
            float pd[2][2] = {{0.f, 0.f}, {0.f, 0.f}};
#pragma unroll
            for (int j = 0; j < 8; ++j) {
                int n0 = wc + j * 8 + (lane & 3) * 2;
                float s0 = __ldg(&v0[n0]), s1 = __ldg(&v0[n0 + 1]);
                float d0 = __ldg(&v1[n0]), d1 = __ldg(&v1[n0 + 1]);
                int hh = j >> 2;
                ps[hh][0] += acc[j][0] * s0 + acc[j][1] * s1;
                ps[hh][1] += acc[j][2] * s0 + acc[j][3] * s1;
                pd[hh][0] += acc[j][0] * d0 + acc[j][1] * d1;
                pd[hh][1] += acc[j][2] * d0 + acc[j][3] * d1;
            }
#pragma unroll
            for (int o = 1; o < 4; o <<= 1) {
#pragma unroll
                for (int hh = 0; hh < 2; ++hh)
#pragma unroll
                    for (int rh = 0; rh < 2; ++rh) {
                        ps[hh][rh] += __shfl_xor_sync(0xFFFFFFFFu, ps[hh][rh], o);
                        pd[hh][rh] += __shfl_xor_sync(0xFFFFFFFFu, pd[hh][rh], o);
                    }
            }
            if ((lane & 3) == 0) {
                int h0 = wc >> 5;
                if (r_g < M) {
                    g_asrc[(size_t)r_g * HEADS + h0]     = ps[0][0] * LOG2E;
                    g_asrc[(size_t)r_g * HEADS + h0 + 1] = ps[1][0] * LOG2E;
                    g_adst[(size_t)r_g * HEADS + h0]     = pd[0][0] * LOG2E;
                    g_adst[(size_t)r_g * HEADS + h0 + 1] = pd[1][0] * LOG2E;
                }
                if (r_g + 8 < M) {
                    g_asrc[(size_t)(r_g + 8) * HEADS + h0]     = ps[0][1] * LOG2E;
                    g_asrc[(size_t)(r_g + 8) * HEADS + h0 + 1] = ps[1][1] * LOG2E;
                    g_adst[(size_t)(r_g + 8) * HEADS + h0]     = pd[0][1] * LOG2E;
                    g_adst[(size_t)(r_g + 8) * HEADS + h0 + 1] = pd[1][1] * LOG2E;
                }
            }
        }
    }
}

// ---------------- gather v4: fp16 h, 2 edges/step, 8 ch/lane, peeled tail, fp16 out ----------------
__global__ void __launch_bounds__(256) gather_kernel(int N)
{
    int node = (blockIdx.x * blockDim.x + threadIdx.x) >> 5;
    if (node >= N) return;
    const int lane = threadIdx.x & 31;
    const int sub  = lane & 15;        // channel group
    const int half = lane >> 4;        // edge parity within a step pair
    const int head = sub >> 2;
    const int chan = sub * 8;

    const int off = g_off[node];
    const int deg = g_deg[node];

    const float ad_my = __ldg(&g_adst[(size_t)node * HEADS + head]);

    float acc[8];
#pragma unroll
    for (int c = 0; c < 8; ++c) acc[c] = 0.f;
    float s_my = 0.f;

    const int nfull = deg & ~31;

    // full 32-edge chunks: no bounds checks
    for (int base = 0; base < nfull; base += 32) {
        int idx = g_srcs[off + base + lane];
#pragma unroll
        for (int j = 0; j < 32; j += 4) {
            int s0 = __shfl_sync(0xFFFFFFFFu, idx, j + half);
            int s1 = __shfl_sync(0xFFFFFFFFu, idx, j + 2 + half);
            float as0 = __ldg(&g_asrc[(size_t)s0 * HEADS + head]);
            float as1 = __ldg(&g_asrc[(size_t)s1 * HEADS + head]);
            uint4 u0 = *reinterpret_cast<const uint4*>(&g_h[(size_t)s0 * CH + chan]);
            uint4 u1 = *reinterpret_cast<const uint4*>(&g_h[(size_t)s1 * CH + chan]);

            float x0 = ex2f(lrelu(as0 + ad_my));
            float x1 = ex2f(lrelu(as1 + ad_my));

            float2 f;
            f = __half22float2(*reinterpret_cast<__half2*>(&u0.x));
            acc[0] = fmaf(x0, f.x, acc[0]); acc[1] = fmaf(x0, f.y, acc[1]);
            f = __half22float2(*reinterpret_cast<__half2*>(&u0.y));
            acc[2] = fmaf(x0, f.x, acc[2]); acc[3] = fmaf(x0, f.y, acc[3]);
            f = __half22float2(*reinterpret_cast<__half2*>(&u0.z));
            acc[4] = fmaf(x0, f.x, acc[4]); acc[5] = fmaf(x0, f.y, acc[5]);
            f = __half22float2(*reinterpret_cast<__half2*>(&u0.w));
            acc[6] = fmaf(x0, f.x, acc[6]); acc[7] = fmaf(x0, f.y, acc[7]);

            f = __half22float2(*reinterpret_cast<__half2*>(&u1.x));
            acc[0] = fmaf(x1, f.x, acc[0]); acc[1] = fmaf(x1, f.y, acc[1]);
            f = __half22float2(*reinterpret_cast<__half2*>(&u1.y));
            acc[2] = fmaf(x1, f.x, acc[2]); acc[3] = fmaf(x1, f.y, acc[3]);
            f = __half22float2(*reinterpret_cast<__half2*>(&u1.z));
            acc[4] = fmaf(x1, f.x, acc[4]); acc[5] = fmaf(x1, f.y, acc[5]);
            f = __half22float2(*reinterpret_cast<__half2*>(&u1.w));
            acc[6] = fmaf(x1, f.x, acc[6]); acc[7] = fmaf(x1, f.y, acc[7]);

            s_my += x0 + x1;
        }
    }

    // partial tail chunk
    if (nfull < deg) {
        int idx = 0;
        if (nfull + lane < deg) idx = g_srcs[off + nfull + lane];
        const int cnt = deg - nfull;
        for (int j = 0; j < cnt; j += 4) {
            int e0 = j + half;
            int e1 = j + 2 + half;
            int s0 = __shfl_sync(0xFFFFFFFFu, idx, e0);
            int s1 = __shfl_sync(0xFFFFFFFFu, idx, e1);
            float as0 = __ldg(&g_asrc[(size_t)s0 * HEADS + head]);
            float as1 = __ldg(&g_asrc[(size_t)s1 * HEADS + head]);
            uint4 u0 = *reinterpret_cast<const uint4*>(&g_h[(size_t)s0 * CH + chan]);
            uint4 u1 = *reinterpret_cast<const uint4*>(&g_h[(size_t)s1 * CH + chan]);

            float x0 = (e0 < cnt) ? ex2f(lrelu(as0 + ad_my)) : 0.f;
            float x1 = (e1 < cnt) ? ex2f(lrelu(as1 + ad_my)) : 0.f;

            float2 f;
            f = __half22float2(*reinterpret_cast<__half2*>(&u0.x));
            acc[0] = fmaf(x0, f.x, acc[0]); acc[1] = fmaf(x0, f.y, acc[1]);
            f = __half22float2(*reinterpret_cast<__half2*>(&u0.y));
            acc[2] = fmaf(x0, f.x, acc[2]); acc[3] = fmaf(x0, f.y, acc[3]);
            f = __half22float2(*reinterpret_cast<__half2*>(&u0.z));
            acc[4] = fmaf(x0, f.x, acc[4]); acc[5] = fmaf(x0, f.y, acc[5]);
            f = __half22float2(*reinterpret_cast<__half2*>(&u0.w));
            acc[6] = fmaf(x0, f.x, acc[6]); acc[7] = fmaf(x0, f.y, acc[7]);

            f = __half22float2(*reinterpret_cast<__half2*>(&u1.x));
            acc[0] = fmaf(x1, f.x, acc[0]); acc[1] = fmaf(x1, f.y, acc[1]);
            f = __half22float2(*reinterpret_cast<__half2*>(&u1.y));
            acc[2] = fmaf(x1, f.x, acc[2]); acc[3] = fmaf(x1, f.y, acc[3]);
            f = __half22float2(*reinterpret_cast<__half2*>(&u1.z));
            acc[4] = fmaf(x1, f.x, acc[4]); acc[5] = fmaf(x1, f.y, acc[5]);
            f = __half22float2(*reinterpret_cast<__half2*>(&u1.w));
            acc[6] = fmaf(x1, f.x, acc[6]); acc[7] = fmaf(x1, f.y, acc[7]);

            s_my += x0 + x1;
        }
    }

#pragma unroll
    for (int c = 0; c < 8; ++c)
        acc[c] += __shfl_xor_sync(0xFFFFFFFFu, acc[c], 16);
    s_my += __shfl_xor_sync(0xFFFFFFFFu, s_my, 16);

    if (half == 0) {
        float inv = 1.f / (s_my + 1e-16f);
        __half2 o0 = __float22half2_rn(make_float2(acc[0] * inv, acc[1] * inv));
        __half2 o1 = __float22half2_rn(make_float2(acc[2] * inv, acc[3] * inv));
        __half2 o2 = __float22half2_rn(make_float2(acc[4] * inv, acc[5] * inv));
        __half2 o3 = __float22half2_rn(make_float2(acc[6] * inv, acc[7] * inv));
        uint4 o;
        o.x = *reinterpret_cast<uint32_t*>(&o0);
        o.y = *reinterpret_cast<uint32_t*>(&o1);
        o.z = *reinterpret_cast<uint32_t*>(&o2);
        o.w = *reinterpret_cast<uint32_t*>(&o3);
        *reinterpret_cast<uint4*>(&g_accum[(size_t)node * CH + chan]) = o;
    }
}

// ---------------- launch ----------------
extern "C" void kernel_launch(void* const* d_in, const int* in_sizes, int n_in,
                              void* d_out, int out_size)
{
    const float* x     = (const float*)d_in[0];
    const int*   ei    = (const int*)  d_in[1];
    const float* W     = (const float*)d_in[2];
    const float* att_s = (const float*)d_in[3];
    const float* att_d = (const float*)d_in[4];
    const float* lin_w = (const float*)d_in[5];
    const float* lin_b = (const float*)d_in[6];
    float* out = (float*)d_out;

    int N = in_sizes[0] / CH;    // 100000
    int E = in_sizes[1] / 2;     // 1600000

    void *p_h, *p_acc, *p_whi, *p_wlo, *p_lwhi, *p_lwlo;
    cudaGetSymbolAddress(&p_h, g_h);
    cudaGetSymbolAddress(&p_acc, g_accum);
    cudaGetSymbolAddress(&p_whi, g_whi);
    cudaGetSymbolAddress(&p_wlo, g_wlo);
    cudaGetSymbolAddress(&p_lwhi, g_lwhi);
    cudaGetSymbolAddress(&p_lwlo, g_lwlo);

    const int SMEM = 98304;
    cudaFuncSetAttribute(gemm_mma<0>, cudaFuncAttributeMaxDynamicSharedMemorySize, SMEM);
    cudaFuncSetAttribute(gemm_mma<1>, cudaFuncAttributeMaxDynamicSharedMemorySize, SMEM);

    int ntiles = (N + 63) / 64;
    int gemm_blocks = (ntiles < 296) ? ntiles : 296;   // persistent, 2/SM

    // fork: csr_build (side stream) || prep + gemm1 (main stream) — proven topology
    cudaStream_t s2;
    cudaStreamCreateWithFlags(&s2, cudaStreamNonBlocking);
    cudaEvent_t ev_fork, ev_join;
    cudaEventCreateWithFlags(&ev_fork, cudaEventDisableTiming);
    cudaEventCreateWithFlags(&ev_join, cudaEventDisableTiming);

    cudaEventRecord(ev_fork, 0);
    cudaStreamWaitEvent(s2, ev_fork, 0);
    csr_build<<<NBLK, CBS, 0, s2>>>(ei, E, N);                                  // 0
    cudaEventRecord(ev_join, s2);

    prep_all<<<128, 256>>>(W, lin_w);                                           // 1
    gemm_mma<0><<<gemm_blocks, 256, SMEM>>>(                                    // 2
        x, (const unsigned char*)p_whi, (const unsigned char*)p_wlo,
        att_s, att_d, p_h, N);

    cudaStreamWaitEvent(0, ev_join, 0);
    gather_kernel<<<(N * 32 + 255) / 256, 256>>>(N);                            // 3 <- profiled
    gemm_mma<1><<<gemm_blocks, 256, SMEM>>>(                                    // 4
        p_acc, (const unsigned char*)p_lwhi, (const unsigned char*)p_lwlo,
        lin_b, nullptr, out, N);
}

// round 15
// speedup vs baseline: 1.1242x; 1.0843x over previous
#include <cuda_runtime.h>
#include <cuda_bf16.h>
#include <cuda_fp16.h>
#include <cstdint>

#define N_NODES 100000
#define N_EDGES 1600000
#define CH 128          // IN_CH = HEADS*HID = OUT_CH = 128
#define HEADS 4
#define HID 32
#define NEG_SLOPE 0.2f
#define NBLK 148
#define CBS 1024
#define DUMMY N_NODES   // dummy src node: asrc=-1e30 -> x=0 exactly

// ---------------- scratch (static device globals; no allocation) ----------------
__device__ __half g_h[(size_t)(N_NODES + 1) * CH]; // x @ W, fp16 (+1 zeroed dummy row)
__device__ __half g_accum[(size_t)N_NODES * CH];   // normalized messages, fp16
__device__ float g_asrc[(size_t)(N_NODES + 1) * HEADS]; // pre-scaled by log2(e); +dummy
__device__ float g_adst[(size_t)N_NODES * HEADS];  // pre-scaled by log2(e)
__device__ int   g_deg[N_NODES];
__device__ int   g_off[N_NODES];
__device__ int   g_pos[N_EDGES];                   // per-edge slot within its dst list
__device__ int   g_srcs[N_EDGES];
__device__ int   g_bsum[NBLK];
__device__ unsigned g_c[8];                        // grid-barrier counters (zero-init)
// pre-swizzled bf16 hi/lo images of W^T and lin_w^T ([n][k] layout, 32KB each)
__device__ __align__(16) unsigned char g_whi[32768];
__device__ __align__(16) unsigned char g_wlo[32768];
__device__ __align__(16) unsigned char g_lwhi[32768];
__device__ __align__(16) unsigned char g_lwlo[32768];

#define LOG2E 1.4426950408889634f

// ---------------- helpers ----------------
__device__ __forceinline__ uint32_t s2u(const void* p) {
    uint32_t a;
    asm("{ .reg .u64 t; cvta.to.shared.u64 t, %1; cvt.u32.u64 %0, t; }" : "=r"(a) : "l"(p));
    return a;
}

// swizzled byte offset inside a [rows][128 bf16] tile (256B rows, XOR-16B-chunk swizzle)
__device__ __forceinline__ uint32_t swz(int row, int col) {
    return (uint32_t)(row * 256 + ((((col >> 3) ^ (row & 7))) << 4) + (col & 7) * 2);
}

#define LDSM4(r, addr) \
    asm volatile("ldmatrix.sync.aligned.m8n8.x4.shared.b16 {%0,%1,%2,%3}, [%4];" \
        : "=r"((r)[0]), "=r"((r)[1]), "=r"((r)[2]), "=r"((r)[3]) : "r"(addr))

#define MMA16816(d, a, b0, b1) \
    asm volatile("mma.sync.aligned.m16n8k16.row.col.f32.bf16.bf16.f32 " \
        "{%0,%1,%2,%3}, {%4,%5,%6,%7}, {%8,%9}, {%0,%1,%2,%3};" \
        : "+f"((d)[0]), "+f"((d)[1]), "+f"((d)[2]), "+f"((d)[3]) \
        : "r"((a)[0]), "r"((a)[1]), "r"((a)[2]), "r"((a)[3]), "r"(b0), "r"(b1))

// fast 2^x and leaky-relu
__device__ __forceinline__ float ex2f(float x) {
    float r;
    asm("ex2.approx.f32 %0, %1;" : "=f"(r) : "f"(x));
    return r;
}
__device__ __forceinline__ float lrelu(float e) {
    return fmaf(fminf(e, 0.f), -(1.f - NEG_SLOPE), e);
}

// ---------------- software grid barrier ----------------
__device__ __forceinline__ void gbar(int ph) {
    __syncthreads();
    if (threadIdx.x == 0) {
        __threadfence();
        atomicAdd(&g_c[ph], 1u);
        while (*(volatile unsigned*)&g_c[ph] < (unsigned)NBLK) { __nanosleep(64); }
        __threadfence();
    }
    __syncthreads();
}

// ---------------- fused CSR build (pos-recording; atomic-free placement) ----------------
__global__ void __launch_bounds__(CBS, 1) csr_build(const int* __restrict__ ei, int E, int N)
{
    __shared__ int sm[CBS];
    const int b = blockIdx.x, t = threadIdx.x;
    const int gt = b * CBS + t;
    const int GS = NBLK * CBS;
    const int CHUNK = (N + NBLK - 1) / NBLK;
    const int base = b * CHUNK;

    for (int i = gt; i < N; i += GS) g_deg[i] = 0;
    gbar(0);

    for (int i = gt; i < E; i += GS) {
        int pos = atomicAdd(&g_deg[ei[E + i]], 1);
        g_pos[i] = pos;
    }
    gbar(1);

    int myv = 0;
    if (t < CHUNK && base + t < N) myv = __ldcg(&g_deg[base + t]);
    sm[t] = myv;
    __syncthreads();
#pragma unroll
    for (int d = 1; d < CBS; d <<= 1) {
        int v2 = (t >= d) ? sm[t - d] : 0;
        __syncthreads();
        sm[t] += v2;
        __syncthreads();
    }
    int incl = sm[t];
    if (t < CHUNK && base + t < N) g_off[base + t] = incl - myv;
    if (t == CBS - 1) g_bsum[b] = incl;
    gbar(2);

    if (b == 0) {
        int v = (t < NBLK) ? __ldcg(&g_bsum[t]) : 0;
        sm[t] = v;
        __syncthreads();
#pragma unroll
        for (int d = 1; d < CBS; d <<= 1) {
            int v2 = (t >= d) ? sm[t - d] : 0;
            __syncthreads();
            sm[t] += v2;
            __syncthreads();
        }
        if (t < NBLK) g_bsum[t] = sm[t] - v;
    }
    gbar(3);

    {
        int boff = __ldcg(&g_bsum[b]);
        if (t < CHUNK && base + t < N)
            g_off[base + t] += boff;
    }
    gbar(4);

    for (int i = gt; i < E; i += GS) {
        int dst = ei[E + i];
        g_srcs[__ldcg(&g_off[dst]) + g_pos[i]] = ei[i];
    }
    gbar(5);

    if (b == 0 && t < 8) g_c[t] = 0;
}

// ---------------- prep: one weight matrix -> bf16 hi/lo, swizzled ----------------
// INIT_DUMMY: also zero g_h's dummy row and set dummy asrc to -1e30
template<bool INIT_DUMMY>
__global__ void prep_w(const float* __restrict__ src,
                       unsigned char* __restrict__ dhi, unsigned char* __restrict__ dlo)
{
    int idx = blockIdx.x * blockDim.x + threadIdx.x;   // 16384
    int n = idx >> 7, k = idx & 127;
    float v = src[k * CH + n];
    __nv_bfloat16 h = __float2bfloat16(v);
    __nv_bfloat16 l = __float2bfloat16(v - __bfloat162float(h));
    uint32_t o = swz(n, k);
    *reinterpret_cast<__nv_bfloat16*>(dhi + o) = h;
    *reinterpret_cast<__nv_bfloat16*>(dlo + o) = l;

    if (INIT_DUMMY && blockIdx.x == 0) {
        int t = threadIdx.x;
        if (t < 64)
            reinterpret_cast<uint32_t*>(&g_h[(size_t)DUMMY * CH])[t] = 0u;
        else if (t < 64 + HEADS)
            g_asrc[(size_t)DUMMY * HEADS + (t - 64)] = -1e30f;
    }
}

// ---------------- tensor-core GEMM (split-bf16 3-product), PERSISTENT blocks ----------------
// MODE 0: A = fp32 x;      C = g_h (fp16) + fused a_src/a_dst epilogue (v0=att_s, v1=att_d)
// MODE 1: A = fp16 accum;  C = out (fp32) with bias(v0) + ReLU
template<int MODE>
__global__ void __launch_bounds__(256, 2) gemm_mma(
    const void* __restrict__ Av,
    const unsigned char* __restrict__ Bhi_g, const unsigned char* __restrict__ Blo_g,
    const float* __restrict__ v0, const float* __restrict__ v1,
    void* __restrict__ Cv, int M)
{
    extern __shared__ __align__(16) unsigned char smem[];
    // layout: A_hi 16K | A_lo 16K | B_hi 32K | B_lo 32K
    const uint32_t sb = s2u(smem);
    const int tid = threadIdx.x, lane = tid & 31, w = tid >> 5;

    // copy B tiles once
    {
        const int4* bh = reinterpret_cast<const int4*>(Bhi_g);
        const int4* bl = reinterpret_cast<const int4*>(Blo_g);
        int4* dh = reinterpret_cast<int4*>(smem + 32768);
        int4* dl = reinterpret_cast<int4*>(smem + 65536);
#pragma unroll
        for (int u = 0; u < 8; ++u) {
            int f = tid + u * 256;
            dh[f] = bh[f];
            dl[f] = bl[f];
        }
    }

    const int wr = (w >> 1) * 16;
    const int wc = (w & 1) * 64;
    const int arow  = wr + (lane & 7) + ((lane >> 3) & 1) * 8;
    const int asel  = lane >> 4;
    const int arow7 = arow & 7;
    const int bg_row = (lane & 7) + ((lane >> 4) & 1) * 8;
    const int bsel   = (lane >> 3) & 1;

    const int ntiles = (M + 63) / 64;
    for (int tile = blockIdx.x; tile < ntiles; tile += gridDim.x) {
        const int row0 = tile * 64;

        __syncthreads();   // protect A smem from previous iteration's readers

        if (MODE == 0) {
            const float* A = (const float*)Av;
#pragma unroll
            for (int u = 0; u < 8; ++u) {
                int f = tid + u * 256;
                int r = f >> 5;
                int c = (f & 31) * 4;
                float4 v = make_float4(0.f, 0.f, 0.f, 0.f);
                if (row0 + r < M)
                    v = *reinterpret_cast<const float4*>(&A[(size_t)(row0 + r) * CH + c]);
                __nv_bfloat162 h01 = __floats2bfloat162_rn(v.x, v.y);
                __nv_bfloat162 h23 = __floats2bfloat162_rn(v.z, v.w);
                __nv_bfloat162 lo01 = __floats2bfloat162_rn(v.x - __bfloat162float(h01.x),
                                                            v.y - __bfloat162float(h01.y));
                __nv_bfloat162 lo23 = __floats2bfloat162_rn(v.z - __bfloat162float(h23.x),
                                                            v.w - __bfloat162float(h23.y));
                uint32_t o = swz(r, c);
                uint2 uh, ul;
                uh.x = *reinterpret_cast<uint32_t*>(&h01);
                uh.y = *reinterpret_cast<uint32_t*>(&h23);
                ul.x = *reinterpret_cast<uint32_t*>(&lo01);
                ul.y = *reinterpret_cast<uint32_t*>(&lo23);
                *reinterpret_cast<uint2*>(smem + o)         = uh;
                *reinterpret_cast<uint2*>(smem + 16384 + o) = ul;
            }
        } else {
            const __half* A = (const __half*)Av;
#pragma unroll
            for (int u = 0; u < 4; ++u) {
                int f = tid + u * 256;          // [0, 1024)
                int r = f >> 4;
                int c = (f & 15) * 8;
                uint4 hv = make_uint4(0u, 0u, 0u, 0u);
                if (row0 + r < M)
                    hv = *reinterpret_cast<const uint4*>(&A[(size_t)(row0 + r) * CH + c]);
                const __half2* hp = reinterpret_cast<const __half2*>(&hv);
                uint32_t hi[4], lo[4];
#pragma unroll
                for (int q = 0; q < 4; ++q) {
                    float2 t = __half22float2(hp[q]);
                    __nv_bfloat162 bh = __floats2bfloat162_rn(t.x, t.y);
                    __nv_bfloat162 bl = __floats2bfloat162_rn(t.x - __bfloat162float(bh.x),
                                                              t.y - __bfloat162float(bh.y));
                    hi[q] = *reinterpret_cast<uint32_t*>(&bh);
                    lo[q] = *reinterpret_cast<uint32_t*>(&bl);
                }
                uint32_t o = swz(r, c);
                *reinterpret_cast<uint4*>(smem + o)         = make_uint4(hi[0], hi[1], hi[2], hi[3]);
                *reinterpret_cast<uint4*>(smem + 16384 + o) = make_uint4(lo[0], lo[1], lo[2], lo[3]);
            }
        }
        __syncthreads();

        float acc[8][4];
#pragma unroll
        for (int j = 0; j < 8; ++j)
#pragma unroll
            for (int q = 0; q < 4; ++q) acc[j][q] = 0.f;

#pragma unroll
        for (int kk = 0; kk < 8; ++kk) {
            uint32_t a_hi[4], a_lo[4];
            uint32_t aaddr = sb + (uint32_t)(arow * 256) +
                             (uint32_t)((((kk * 2 + asel) ^ arow7)) << 4);
            LDSM4(a_hi, aaddr);
            LDSM4(a_lo, aaddr + 16384);

            uint32_t b_hi[16], b_lo[16];
#pragma unroll
            for (int g = 0; g < 4; ++g) {
                int brow = wc + g * 16 + bg_row;
                uint32_t baddr = sb + 32768 + (uint32_t)(brow * 256) +
                                 (uint32_t)((((kk * 2 + bsel) ^ (brow & 7))) << 4);
                LDSM4(&b_hi[g * 4], baddr);
                LDSM4(&b_lo[g * 4], baddr + 32768);
            }

#pragma unroll
            for (int j = 0; j < 8; ++j) {
                int i0 = (j >> 1) * 4 + (j & 1) * 2;
                MMA16816(acc[j], a_hi, b_hi[i0], b_hi[i0 + 1]);
            }
#pragma unroll
            for (int j = 0; j < 8; ++j) {
                int i0 = (j >> 1) * 4 + (j & 1) * 2;
                MMA16816(acc[j], a_hi, b_lo[i0], b_lo[i0 + 1]);
            }
#pragma unroll
            for (int j = 0; j < 8; ++j) {
                int i0 = (j >> 1) * 4 + (j & 1) * 2;
                MMA16816(acc[j], a_lo, b_hi[i0], b_hi[i0 + 1]);
            }
        }

        const int r_g = row0 + wr + (lane >> 2);
#pragma unroll
        for (int j = 0; j < 8; ++j) {
            int n0 = wc + j * 8 + (lane & 3) * 2;
            if (MODE == 1) {
                float* C = (float*)Cv;
                float b0 = __ldg(&v0[n0]), b1 = __ldg(&v0[n0 + 1]);
                float2 o0, o1;
                o0.x = fmaxf(acc[j][0] + b0, 0.f); o0.y = fmaxf(acc[j][1] + b1, 0.f);
                o1.x = fmaxf(acc[j][2] + b0, 0.f); o1.y = fmaxf(acc[j][3] + b1, 0.f);
                if (r_g < M)
                    *reinterpret_cast<float2*>(&C[(size_t)r_g * CH + n0]) = o0;
                if (r_g + 8 < M)
                    *reinterpret_cast<float2*>(&C[(size_t)(r_g + 8) * CH + n0]) = o1;
            } else {
                __half* C = (__half*)Cv;
                __half2 o0 = __float22half2_rn(make_float2(acc[j][0], acc[j][1]));
                __half2 o1 = __float22half2_rn(make_float2(acc[j][2], acc[j][3]));
                if (r_g < M)
                    *reinterpret_cast<__half2*>(&C[(size_t)r_g * CH + n0]) = o0;
                if (r_g + 8 < M)
                    *reinterpret_cast<__half2*>(&C[(size_t)(r_g + 8) * CH + n0]) = o1;
            }
        }

        if (MODE == 0) {
            // fused att projections, pre-scaled by log2(e)
            float ps[2][2] = {{0.f, 0.f}, {0.f, 0.f}};
            float pd[2][2] = {{0.f, 0.f}, {0.f, 0.f}};
#pragma unroll
            for (int j = 0; j < 8; ++j) {
                int n0 = wc + j * 8 + (lane & 3) * 2;
                float s0 = __ldg(&v0[n0]), s1 = __ldg(&v0[n0 + 1]);
                float d0 = __ldg(&v1[n0]), d1 = __ldg(&v1[n0 + 1]);
                int hh = j >> 2;
                ps[hh][0] += acc[j][0] * s0 + acc[j][1] * s1;
                ps[hh][1] += acc[j][2] * s0 + acc[j][3] * s1;
                pd[hh][0] += acc[j][0] * d0 + acc[j][1] * d1;
                pd[hh][1] += acc[j][2] * d0 + acc[j][3] * d1;
            }
#pragma unroll
            for (int o = 1; o < 4; o <<= 1) {
#pragma unroll
                for (int hh = 0; hh < 2; ++hh)
#pragma unroll
                    for (int rh = 0; rh < 2; ++rh) {
                        ps[hh][rh] += __shfl_xor_sync(0xFFFFFFFFu, ps[hh][rh], o);
                        pd[hh][rh] += __shfl_xor_sync(0xFFFFFFFFu, pd[hh][rh], o);
                    }
            }
            if ((lane & 3) == 0) {
                int h0 = wc >> 5;
                if (r_g < M) {
                    g_asrc[(size_t)r_g * HEADS + h0]     = ps[0][0] * LOG2E;
                    g_asrc[(size_t)r_g * HEADS + h0 + 1] = ps[1][0] * LOG2E;
                    g_adst[(size_t)r_g * HEADS + h0]     = pd[0][0] * LOG2E;
                    g_adst[(size_t)r_g * HEADS + h0 + 1] = pd[1][0] * LOG2E;
                }
                if (r_g + 8 < M) {
                    g_asrc[(size_t)(r_g + 8) * HEADS + h0]     = ps[0][1] * LOG2E;
                    g_asrc[(size_t)(r_g + 8) * HEADS + h0 + 1] = ps[1][1] * LOG2E;
                    g_adst[(size_t)(r_g + 8) * HEADS + h0]     = pd[0][1] * LOG2E;
                    g_adst[(size_t)(r_g + 8) * HEADS + h0 + 1] = pd[1][1] * LOG2E;
                }
            }
        }
    }
}

// ---------------- gather v5: fp16 h, 2 edges/step, 8 ch/lane, guard-free via dummy ----------------
__global__ void __launch_bounds__(256) gather_kernel(int N)
{
    int node = (blockIdx.x * blockDim.x + threadIdx.x) >> 5;
    if (node >= N) return;
    const int lane = threadIdx.x & 31;
    const int sub  = lane & 15;        // channel group
    const int half = lane >> 4;        // edge parity within a step pair
    const int head = sub >> 2;
    const int chan = sub * 8;

    const int off = g_off[node];
    const int deg = g_deg[node];

    const float ad_my = __ldg(&g_adst[(size_t)node * HEADS + head]);

    float acc[8];
#pragma unroll
    for (int c = 0; c < 8; ++c) acc[c] = 0.f;
    float s_my = 0.f;

    for (int base = 0; base < deg; base += 32) {
        int idx = DUMMY;                       // out-of-range lanes -> x = 0 exactly
        if (base + lane < deg) idx = g_srcs[off + base + lane];
        int cnt = min(32, deg - base);
        for (int j = 0; j < cnt; j += 4) {
            int s0 = __shfl_sync(0xFFFFFFFFu, idx, j + half);
            int s1 = __shfl_sync(0xFFFFFFFFu, idx, j + 2 + half);
            float as0 = __ldg(&g_asrc[(size_t)s0 * HEADS + head]);
            float as1 = __ldg(&g_asrc[(size_t)s1 * HEADS + head]);
            uint4 u0 = *reinterpret_cast<const uint4*>(&g_h[(size_t)s0 * CH + chan]);
            uint4 u1 = *reinterpret_cast<const uint4*>(&g_h[(size_t)s1 * CH + chan]);

            float x0 = ex2f(lrelu(as0 + ad_my));
            float x1 = ex2f(lrelu(as1 + ad_my));

            float2 f;
            f = __half22float2(*reinterpret_cast<__half2*>(&u0.x));
            acc[0] = fmaf(x0, f.x, acc[0]); acc[1] = fmaf(x0, f.y, acc[1]);
            f = __half22float2(*reinterpret_cast<__half2*>(&u0.y));
            acc[2] = fmaf(x0, f.x, acc[2]); acc[3] = fmaf(x0, f.y, acc[3]);
            f = __half22float2(*reinterpret_cast<__half2*>(&u0.z));
            acc[4] = fmaf(x0, f.x, acc[4]); acc[5] = fmaf(x0, f.y, acc[5]);
            f = __half22float2(*reinterpret_cast<__half2*>(&u0.w));
            acc[6] = fmaf(x0, f.x, acc[6]); acc[7] = fmaf(x0, f.y, acc[7]);

            f = __half22float2(*reinterpret_cast<__half2*>(&u1.x));
            acc[0] = fmaf(x1, f.x, acc[0]); acc[1] = fmaf(x1, f.y, acc[1]);
            f = __half22float2(*reinterpret_cast<__half2*>(&u1.y));
            acc[2] = fmaf(x1, f.x, acc[2]); acc[3] = fmaf(x1, f.y, acc[3]);
            f = __half22float2(*reinterpret_cast<__half2*>(&u1.z));
            acc[4] = fmaf(x1, f.x, acc[4]); acc[5] = fmaf(x1, f.y, acc[5]);
            f = __half22float2(*reinterpret_cast<__half2*>(&u1.w));
            acc[6] = fmaf(x1, f.x, acc[6]); acc[7] = fmaf(x1, f.y, acc[7]);

            s_my += x0 + x1;
        }
    }

#pragma unroll
    for (int c = 0; c < 8; ++c)
        acc[c] += __shfl_xor_sync(0xFFFFFFFFu, acc[c], 16);
    s_my += __shfl_xor_sync(0xFFFFFFFFu, s_my, 16);

    if (half == 0) {
        float inv = 1.f / (s_my + 1e-16f);
        __half2 o0 = __float22half2_rn(make_float2(acc[0] * inv, acc[1] * inv));
        __half2 o1 = __float22half2_rn(make_float2(acc[2] * inv, acc[3] * inv));
        __half2 o2 = __float22half2_rn(make_float2(acc[4] * inv, acc[5] * inv));
        __half2 o3 = __float22half2_rn(make_float2(acc[6] * inv, acc[7] * inv));
        uint4 o;
        o.x = *reinterpret_cast<uint32_t*>(&o0);
        o.y = *reinterpret_cast<uint32_t*>(&o1);
        o.z = *reinterpret_cast<uint32_t*>(&o2);
        o.w = *reinterpret_cast<uint32_t*>(&o3);
        *reinterpret_cast<uint4*>(&g_accum[(size_t)node * CH + chan]) = o;
    }
}

// ---------------- launch ----------------
extern "C" void kernel_launch(void* const* d_in, const int* in_sizes, int n_in,
                              void* d_out, int out_size)
{
    const float* x     = (const float*)d_in[0];
    const int*   ei    = (const int*)  d_in[1];
    const float* W     = (const float*)d_in[2];
    const float* att_s = (const float*)d_in[3];
    const float* att_d = (const float*)d_in[4];
    const float* lin_w = (const float*)d_in[5];
    const float* lin_b = (const float*)d_in[6];
    float* out = (float*)d_out;

    int N = in_sizes[0] / CH;    // 100000
    int E = in_sizes[1] / 2;     // 1600000

    void *p_h, *p_acc, *p_whi, *p_wlo, *p_lwhi, *p_lwlo;
    cudaGetSymbolAddress(&p_h, g_h);
    cudaGetSymbolAddress(&p_acc, g_accum);
    cudaGetSymbolAddress(&p_whi, g_whi);
    cudaGetSymbolAddress(&p_wlo, g_wlo);
    cudaGetSymbolAddress(&p_lwhi, g_lwhi);
    cudaGetSymbolAddress(&p_lwlo, g_lwlo);

    const int SMEM = 98304;
    cudaFuncSetAttribute(gemm_mma<0>, cudaFuncAttributeMaxDynamicSharedMemorySize, SMEM);
    cudaFuncSetAttribute(gemm_mma<1>, cudaFuncAttributeMaxDynamicSharedMemorySize, SMEM);

    int ntiles = (N + 63) / 64;
    int gemm_blocks = (ntiles < 296) ? ntiles : 296;   // persistent, 2/SM

    // fork: csr_build (side stream) || prep + gemm1 (main stream) — proven topology
    cudaStream_t s2;
    cudaStreamCreateWithFlags(&s2, cudaStreamNonBlocking);
    cudaEvent_t ev_fork, ev_join;
    cudaEventCreateWithFlags(&ev_fork, cudaEventDisableTiming);
    cudaEventCreateWithFlags(&ev_join, cudaEventDisableTiming);

    cudaEventRecord(ev_fork, 0);
    cudaStreamWaitEvent(s2, ev_fork, 0);
    csr_build<<<NBLK, CBS, 0, s2>>>(ei, E, N);                                  // 0
    cudaEventRecord(ev_join, s2);

    prep_w<true><<<64, 256>>>(W, (unsigned char*)p_whi, (unsigned char*)p_wlo); // 1
    prep_w<false><<<64, 256>>>(lin_w, (unsigned char*)p_lwhi, (unsigned char*)p_lwlo); // 2
    gemm_mma<0><<<gemm_blocks, 256, SMEM>>>(                                    // 3 <- profiled
        x, (const unsigned char*)p_whi, (const unsigned char*)p_wlo,
        att_s, att_d, p_h, N);

    cudaStreamWaitEvent(0, ev_join, 0);
    gather_kernel<<<(N * 32 + 255) / 256, 256>>>(N);                            // 4
    gemm_mma<1><<<gemm_blocks, 256, SMEM>>>(                                    // 5
        p_acc, (const unsigned char*)p_lwhi, (const unsigned char*)p_lwlo,
        lin_b, nullptr, out, N);
}

// round 16
// speedup vs baseline: 1.1446x; 1.0181x over previous
#include <cuda_runtime.h>
#include <cuda_bf16.h>
#include <cuda_fp16.h>
#include <cstdint>

#define N_NODES 100000
#define N_EDGES 1600000
#define CH 128          // IN_CH = HEADS*HID = OUT_CH = 128
#define HEADS 4
#define HID 32
#define NEG_SLOPE 0.2f
#define NBLK 148
#define CBS 1024
#define DUMMY N_NODES   // dummy src node: asrc=-1e30 -> x=0 exactly

// ---------------- scratch (static device globals; no allocation) ----------------
__device__ __half g_h[(size_t)(N_NODES + 1) * CH]; // x @ W, fp16 (+1 zeroed dummy row)
__device__ __half g_accum[(size_t)N_NODES * CH];   // normalized messages, fp16
__device__ float g_asrc[(size_t)(N_NODES + 1) * HEADS]; // pre-scaled by log2(e); +dummy
__device__ float g_adst[(size_t)N_NODES * HEADS];  // pre-scaled by log2(e)
__device__ int   g_deg[N_NODES];
__device__ int   g_off[N_NODES];
__device__ int   g_pos[N_EDGES];                   // per-edge slot within its dst list
__device__ int   g_srcs[N_EDGES];
__device__ int   g_bsum[NBLK];
__device__ unsigned g_c[8];                        // grid-barrier counters (zero-init)
// pre-swizzled bf16 hi/lo images of W^T and lin_w^T ([n][k] layout, 32KB each)
__device__ __align__(16) unsigned char g_whi[32768];
__device__ __align__(16) unsigned char g_wlo[32768];
__device__ __align__(16) unsigned char g_lwhi[32768];
__device__ __align__(16) unsigned char g_lwlo[32768];

#define LOG2E 1.4426950408889634f

// ---------------- helpers ----------------
__device__ __forceinline__ uint32_t s2u(const void* p) {
    uint32_t a;
    asm("{ .reg .u64 t; cvta.to.shared.u64 t, %1; cvt.u32.u64 %0, t; }" : "=r"(a) : "l"(p));
    return a;
}

// swizzled byte offset inside a [rows][128 bf16] tile (256B rows, XOR-16B-chunk swizzle)
__device__ __forceinline__ uint32_t swz(int row, int col) {
    return (uint32_t)(row * 256 + ((((col >> 3) ^ (row & 7))) << 4) + (col & 7) * 2);
}

#define LDSM4(r, addr) \
    asm volatile("ldmatrix.sync.aligned.m8n8.x4.shared.b16 {%0,%1,%2,%3}, [%4];" \
        : "=r"((r)[0]), "=r"((r)[1]), "=r"((r)[2]), "=r"((r)[3]) : "r"(addr))

#define MMA16816(d, a, b0, b1) \
    asm volatile("mma.sync.aligned.m16n8k16.row.col.f32.bf16.bf16.f32 " \
        "{%0,%1,%2,%3}, {%4,%5,%6,%7}, {%8,%9}, {%0,%1,%2,%3};" \
        : "+f"((d)[0]), "+f"((d)[1]), "+f"((d)[2]), "+f"((d)[3]) \
        : "r"((a)[0]), "r"((a)[1]), "r"((a)[2]), "r"((a)[3]), "r"(b0), "r"(b1))

// fast 2^x and leaky-relu
__device__ __forceinline__ float ex2f(float x) {
    float r;
    asm("ex2.approx.f32 %0, %1;" : "=f"(r) : "f"(x));
    return r;
}
__device__ __forceinline__ float lrelu(float e) {
    return fmaf(fminf(e, 0.f), -(1.f - NEG_SLOPE), e);
}

// ---------------- software grid barrier ----------------
__device__ __forceinline__ void gbar(int ph) {
    __syncthreads();
    if (threadIdx.x == 0) {
        __threadfence();
        atomicAdd(&g_c[ph], 1u);
        while (*(volatile unsigned*)&g_c[ph] < (unsigned)NBLK) { __nanosleep(64); }
        __threadfence();
    }
    __syncthreads();
}

// ---------------- fused CSR build (pos-recording; atomic-free placement) ----------------
__global__ void __launch_bounds__(CBS, 1) csr_build(const int* __restrict__ ei, int E, int N)
{
    __shared__ int sm[CBS];
    const int b = blockIdx.x, t = threadIdx.x;
    const int gt = b * CBS + t;
    const int GS = NBLK * CBS;
    const int CHUNK = (N + NBLK - 1) / NBLK;
    const int base = b * CHUNK;

    for (int i = gt; i < N; i += GS) g_deg[i] = 0;
    gbar(0);

    for (int i = gt; i < E; i += GS) {
        int pos = atomicAdd(&g_deg[ei[E + i]], 1);
        g_pos[i] = pos;
    }
    gbar(1);

    int myv = 0;
    if (t < CHUNK && base + t < N) myv = __ldcg(&g_deg[base + t]);
    sm[t] = myv;
    __syncthreads();
#pragma unroll
    for (int d = 1; d < CBS; d <<= 1) {
        int v2 = (t >= d) ? sm[t - d] : 0;
        __syncthreads();
        sm[t] += v2;
        __syncthreads();
    }
    int incl = sm[t];
    if (t < CHUNK && base + t < N) g_off[base + t] = incl - myv;
    if (t == CBS - 1) g_bsum[b] = incl;
    gbar(2);

    if (b == 0) {
        int v = (t < NBLK) ? __ldcg(&g_bsum[t]) : 0;
        sm[t] = v;
        __syncthreads();
#pragma unroll
        for (int d = 1; d < CBS; d <<= 1) {
            int v2 = (t >= d) ? sm[t - d] : 0;
            __syncthreads();
            sm[t] += v2;
            __syncthreads();
        }
        if (t < NBLK) g_bsum[t] = sm[t] - v;
    }
    gbar(3);

    {
        int boff = __ldcg(&g_bsum[b]);
        if (t < CHUNK && base + t < N)
            g_off[base + t] += boff;
    }
    gbar(4);

    for (int i = gt; i < E; i += GS) {
        int dst = ei[E + i];
        g_srcs[__ldcg(&g_off[dst]) + g_pos[i]] = ei[i];
    }
    gbar(5);

    if (b == 0 && t < 8) g_c[t] = 0;
}

// ---------------- prep: one weight matrix -> bf16 hi/lo, swizzled ----------------
template<bool INIT_DUMMY>
__global__ void prep_w(const float* __restrict__ src,
                       unsigned char* __restrict__ dhi, unsigned char* __restrict__ dlo)
{
    int idx = blockIdx.x * blockDim.x + threadIdx.x;   // 16384
    int n = idx >> 7, k = idx & 127;
    float v = src[k * CH + n];
    __nv_bfloat16 h = __float2bfloat16(v);
    __nv_bfloat16 l = __float2bfloat16(v - __bfloat162float(h));
    uint32_t o = swz(n, k);
    *reinterpret_cast<__nv_bfloat16*>(dhi + o) = h;
    *reinterpret_cast<__nv_bfloat16*>(dlo + o) = l;

    if (INIT_DUMMY && blockIdx.x == 0) {
        int t = threadIdx.x;
        if (t < 64)
            reinterpret_cast<uint32_t*>(&g_h[(size_t)DUMMY * CH])[t] = 0u;
        else if (t < 64 + HEADS)
            g_asrc[(size_t)DUMMY * HEADS + (t - 64)] = -1e30f;
    }
}

// ---------------- tensor-core GEMM (split-bf16 3-product), PERSISTENT blocks ----------------
// Warp tile 32 rows x 32 cols (2x4 warp grid): 8 LDSM4/kk instead of 10.
// MODE 0: A = fp32 x;      C = g_h (fp16) + fused a_src/a_dst epilogue (v0=att_s, v1=att_d)
// MODE 1: A = fp16 accum;  C = out (fp32) with bias(v0) + ReLU
template<int MODE>
__global__ void __launch_bounds__(256, 2) gemm_mma(
    const void* __restrict__ Av,
    const unsigned char* __restrict__ Bhi_g, const unsigned char* __restrict__ Blo_g,
    const float* __restrict__ v0, const float* __restrict__ v1,
    void* __restrict__ Cv, int M)
{
    extern __shared__ __align__(16) unsigned char smem[];
    // layout: A_hi 16K | A_lo 16K | B_hi 32K | B_lo 32K
    const uint32_t sb = s2u(smem);
    const int tid = threadIdx.x, lane = tid & 31, w = tid >> 5;

    // copy B tiles once
    {
        const int4* bh = reinterpret_cast<const int4*>(Bhi_g);
        const int4* bl = reinterpret_cast<const int4*>(Blo_g);
        int4* dh = reinterpret_cast<int4*>(smem + 32768);
        int4* dl = reinterpret_cast<int4*>(smem + 65536);
#pragma unroll
        for (int u = 0; u < 8; ++u) {
            int f = tid + u * 256;
            dh[f] = bh[f];
            dl[f] = bl[f];
        }
    }

    const int wr = (w & 1) * 32;       // warp rows [wr, wr+32)
    const int wc = (w >> 1) * 32;      // warp cols [wc, wc+32) -> exactly one head
    const int arow  = wr + (lane & 7) + ((lane >> 3) & 1) * 8;
    const int asel  = lane >> 4;
    const int arow7 = arow & 7;
    const int bg_row = (lane & 7) + ((lane >> 4) & 1) * 8;
    const int bsel   = (lane >> 3) & 1;
    const uint32_t brow_base = (uint32_t)(32768 + (wc + bg_row) * 256);

    const int ntiles = (M + 63) / 64;
    for (int tile = blockIdx.x; tile < ntiles; tile += gridDim.x) {
        const int row0 = tile * 64;

        __syncthreads();   // protect A smem from previous iteration's readers

        if (MODE == 0) {
            const float* A = (const float*)Av;
#pragma unroll
            for (int u = 0; u < 8; ++u) {
                int f = tid + u * 256;
                int r = f >> 5;
                int c = (f & 31) * 4;
                float4 v = make_float4(0.f, 0.f, 0.f, 0.f);
                if (row0 + r < M)
                    v = *reinterpret_cast<const float4*>(&A[(size_t)(row0 + r) * CH + c]);
                __nv_bfloat162 h01 = __floats2bfloat162_rn(v.x, v.y);
                __nv_bfloat162 h23 = __floats2bfloat162_rn(v.z, v.w);
                __nv_bfloat162 lo01 = __floats2bfloat162_rn(v.x - __bfloat162float(h01.x),
                                                            v.y - __bfloat162float(h01.y));
                __nv_bfloat162 lo23 = __floats2bfloat162_rn(v.z - __bfloat162float(h23.x),
                                                            v.w - __bfloat162float(h23.y));
                uint32_t o = swz(r, c);
                uint2 uh, ul;
                uh.x = *reinterpret_cast<uint32_t*>(&h01);
                uh.y = *reinterpret_cast<uint32_t*>(&h23);
                ul.x = *reinterpret_cast<uint32_t*>(&lo01);
                ul.y = *reinterpret_cast<uint32_t*>(&lo23);
                *reinterpret_cast<uint2*>(smem + o)         = uh;
                *reinterpret_cast<uint2*>(smem + 16384 + o) = ul;
            }
        } else {
            const __half* A = (const __half*)Av;
#pragma unroll
            for (int u = 0; u < 4; ++u) {
                int f = tid + u * 256;          // [0, 1024)
                int r = f >> 4;
                int c = (f & 15) * 8;
                uint4 hv = make_uint4(0u, 0u, 0u, 0u);
                if (row0 + r < M)
                    hv = *reinterpret_cast<const uint4*>(&A[(size_t)(row0 + r) * CH + c]);
                const __half2* hp = reinterpret_cast<const __half2*>(&hv);
                uint32_t hi[4], lo[4];
#pragma unroll
                for (int q = 0; q < 4; ++q) {
                    float2 t = __half22float2(hp[q]);
                    __nv_bfloat162 bh = __floats2bfloat162_rn(t.x, t.y);
                    __nv_bfloat162 bl = __floats2bfloat162_rn(t.x - __bfloat162float(bh.x),
                                                              t.y - __bfloat162float(bh.y));
                    hi[q] = *reinterpret_cast<uint32_t*>(&bh);
                    lo[q] = *reinterpret_cast<uint32_t*>(&bl);
                }
                uint32_t o = swz(r, c);
                *reinterpret_cast<uint4*>(smem + o)         = make_uint4(hi[0], hi[1], hi[2], hi[3]);
                *reinterpret_cast<uint4*>(smem + 16384 + o) = make_uint4(lo[0], lo[1], lo[2], lo[3]);
            }
        }
        __syncthreads();

        float acc[2][4][4];   // [m16 tile][n8 tile][frag]
#pragma unroll
        for (int p = 0; p < 2; ++p)
#pragma unroll
            for (int j = 0; j < 4; ++j)
#pragma unroll
                for (int q = 0; q < 4; ++q) acc[p][j][q] = 0.f;

#pragma unroll
        for (int kk = 0; kk < 8; ++kk) {
            const uint32_t kxor = (uint32_t)(((kk * 2 + asel) ^ arow7) << 4);
            const uint32_t aaddr = sb + (uint32_t)(arow * 256) + kxor;
            uint32_t a_hi[8], a_lo[8];
            LDSM4(&a_hi[0], aaddr);
            LDSM4(&a_hi[4], aaddr + 4096);           // +16 rows, same xor (16 % 8 == 0)
            LDSM4(&a_lo[0], aaddr + 16384);
            LDSM4(&a_lo[4], aaddr + 16384 + 4096);

            const uint32_t bxor = (uint32_t)(((kk * 2 + bsel) ^ (bg_row & 7)) << 4);
            const uint32_t baddr = sb + brow_base + bxor;
            uint32_t b_hi[8], b_lo[8];
            LDSM4(&b_hi[0], baddr);
            LDSM4(&b_hi[4], baddr + 4096);           // +16 cols
            LDSM4(&b_lo[0], baddr + 32768);
            LDSM4(&b_lo[4], baddr + 32768 + 4096);

#pragma unroll
            for (int p = 0; p < 2; ++p)
#pragma unroll
                for (int j = 0; j < 4; ++j) {
                    int i0 = (j >> 1) * 4 + (j & 1) * 2;
                    MMA16816(acc[p][j], &a_hi[p * 4], b_hi[i0], b_hi[i0 + 1]);
                }
#pragma unroll
            for (int p = 0; p < 2; ++p)
#pragma unroll
                for (int j = 0; j < 4; ++j) {
                    int i0 = (j >> 1) * 4 + (j & 1) * 2;
                    MMA16816(acc[p][j], &a_hi[p * 4], b_lo[i0], b_lo[i0 + 1]);
                }
#pragma unroll
            for (int p = 0; p < 2; ++p)
#pragma unroll
                for (int j = 0; j < 4; ++j) {
                    int i0 = (j >> 1) * 4 + (j & 1) * 2;
                    MMA16816(acc[p][j], &a_lo[p * 4], b_hi[i0], b_hi[i0 + 1]);
                }
        }

#pragma unroll
        for (int p = 0; p < 2; ++p) {
            const int r_g = row0 + wr + p * 16 + (lane >> 2);
#pragma unroll
            for (int j = 0; j < 4; ++j) {
                int n0 = wc + j * 8 + (lane & 3) * 2;
                if (MODE == 1) {
                    float* C = (float*)Cv;
                    float b0 = __ldg(&v0[n0]), b1 = __ldg(&v0[n0 + 1]);
                    float2 o0, o1;
                    o0.x = fmaxf(acc[p][j][0] + b0, 0.f); o0.y = fmaxf(acc[p][j][1] + b1, 0.f);
                    o1.x = fmaxf(acc[p][j][2] + b0, 0.f); o1.y = fmaxf(acc[p][j][3] + b1, 0.f);
                    if (r_g < M)
                        *reinterpret_cast<float2*>(&C[(size_t)r_g * CH + n0]) = o0;
                    if (r_g + 8 < M)
                        *reinterpret_cast<float2*>(&C[(size_t)(r_g + 8) * CH + n0]) = o1;
                } else {
                    __half* C = (__half*)Cv;
                    __half2 o0 = __float22half2_rn(make_float2(acc[p][j][0], acc[p][j][1]));
                    __half2 o1 = __float22half2_rn(make_float2(acc[p][j][2], acc[p][j][3]));
                    if (r_g < M)
                        *reinterpret_cast<__half2*>(&C[(size_t)r_g * CH + n0]) = o0;
                    if (r_g + 8 < M)
                        *reinterpret_cast<__half2*>(&C[(size_t)(r_g + 8) * CH + n0]) = o1;
                }
            }
        }

        if (MODE == 0) {
            // fused att projections: this warp covers exactly one head (wc/32)
            float ps[2][2] = {{0.f, 0.f}, {0.f, 0.f}};   // [m16 tile][row-half]
            float pd[2][2] = {{0.f, 0.f}, {0.f, 0.f}};
#pragma unroll
            for (int p = 0; p < 2; ++p)
#pragma unroll
                for (int j = 0; j < 4; ++j) {
                    int n0 = wc + j * 8 + (lane & 3) * 2;
                    float s0 = __ldg(&v0[n0]), s1 = __ldg(&v0[n0 + 1]);
                    float d0 = __ldg(&v1[n0]), d1 = __ldg(&v1[n0 + 1]);
                    ps[p][0] += acc[p][j][0] * s0 + acc[p][j][1] * s1;
                    ps[p][1] += acc[p][j][2] * s0 + acc[p][j][3] * s1;
                    pd[p][0] += acc[p][j][0] * d0 + acc[p][j][1] * d1;
                    pd[p][1] += acc[p][j][2] * d0 + acc[p][j][3] * d1;
                }
#pragma unroll
            for (int o = 1; o < 4; o <<= 1) {
#pragma unroll
                for (int p = 0; p < 2; ++p)
#pragma unroll
                    for (int rh = 0; rh < 2; ++rh) {
                        ps[p][rh] += __shfl_xor_sync(0xFFFFFFFFu, ps[p][rh], o);
                        pd[p][rh] += __shfl_xor_sync(0xFFFFFFFFu, pd[p][rh], o);
                    }
            }
            if ((lane & 3) == 0) {
                int h0 = wc >> 5;
#pragma unroll
                for (int p = 0; p < 2; ++p) {
                    int r_g = row0 + wr + p * 16 + (lane >> 2);
                    if (r_g < M) {
                        g_asrc[(size_t)r_g * HEADS + h0] = ps[p][0] * LOG2E;
                        g_adst[(size_t)r_g * HEADS + h0] = pd[p][0] * LOG2E;
                    }
                    if (r_g + 8 < M) {
                        g_asrc[(size_t)(r_g + 8) * HEADS + h0] = ps[p][1] * LOG2E;
                        g_adst[(size_t)(r_g + 8) * HEADS + h0] = pd[p][1] * LOG2E;
                    }
                }
            }
        }
    }
}

// ---------------- gather v5: fp16 h, 2 edges/step, 8 ch/lane, guard-free via dummy ----------------
__global__ void __launch_bounds__(256) gather_kernel(int N)
{
    int node = (blockIdx.x * blockDim.x + threadIdx.x) >> 5;
    if (node >= N) return;
    const int lane = threadIdx.x & 31;
    const int sub  = lane & 15;        // channel group
    const int half = lane >> 4;        // edge parity within a step pair
    const int head = sub >> 2;
    const int chan = sub * 8;

    const int off = g_off[node];
    const int deg = g_deg[node];

    const float ad_my = __ldg(&g_adst[(size_t)node * HEADS + head]);

    float acc[8];
#pragma unroll
    for (int c = 0; c < 8; ++c) acc[c] = 0.f;
    float s_my = 0.f;

    for (int base = 0; base < deg; base += 32) {
        int idx = DUMMY;                       // out-of-range lanes -> x = 0 exactly
        if (base + lane < deg) idx = g_srcs[off + base + lane];
        int cnt = min(32, deg - base);
        for (int j = 0; j < cnt; j += 4) {
            int s0 = __shfl_sync(0xFFFFFFFFu, idx, j + half);
            int s1 = __shfl_sync(0xFFFFFFFFu, idx, j + 2 + half);
            float as0 = __ldg(&g_asrc[(size_t)s0 * HEADS + head]);
            float as1 = __ldg(&g_asrc[(size_t)s1 * HEADS + head]);
            uint4 u0 = *reinterpret_cast<const uint4*>(&g_h[(size_t)s0 * CH + chan]);
            uint4 u1 = *reinterpret_cast<const uint4*>(&g_h[(size_t)s1 * CH + chan]);

            float x0 = ex2f(lrelu(as0 + ad_my));
            float x1 = ex2f(lrelu(as1 + ad_my));

            float2 f;
            f = __half22float2(*reinterpret_cast<__half2*>(&u0.x));
            acc[0] = fmaf(x0, f.x, acc[0]); acc[1] = fmaf(x0, f.y, acc[1]);
            f = __half22float2(*reinterpret_cast<__half2*>(&u0.y));
            acc[2] = fmaf(x0, f.x, acc[2]); acc[3] = fmaf(x0, f.y, acc[3]);
            f = __half22float2(*reinterpret_cast<__half2*>(&u0.z));
            acc[4] = fmaf(x0, f.x, acc[4]); acc[5] = fmaf(x0, f.y, acc[5]);
            f = __half22float2(*reinterpret_cast<__half2*>(&u0.w));
            acc[6] = fmaf(x0, f.x, acc[6]); acc[7] = fmaf(x0, f.y, acc[7]);

            f = __half22float2(*reinterpret_cast<__half2*>(&u1.x));
            acc[0] = fmaf(x1, f.x, acc[0]); acc[1] = fmaf(x1, f.y, acc[1]);
            f = __half22float2(*reinterpret_cast<__half2*>(&u1.y));
            acc[2] = fmaf(x1, f.x, acc[2]); acc[3] = fmaf(x1, f.y, acc[3]);
            f = __half22float2(*reinterpret_cast<__half2*>(&u1.z));
            acc[4] = fmaf(x1, f.x, acc[4]); acc[5] = fmaf(x1, f.y, acc[5]);
            f = __half22float2(*reinterpret_cast<__half2*>(&u1.w));
            acc[6] = fmaf(x1, f.x, acc[6]); acc[7] = fmaf(x1, f.y, acc[7]);

            s_my += x0 + x1;
        }
    }

#pragma unroll
    for (int c = 0; c < 8; ++c)
        acc[c] += __shfl_xor_sync(0xFFFFFFFFu, acc[c], 16);
    s_my += __shfl_xor_sync(0xFFFFFFFFu, s_my, 16);

    if (half == 0) {
        float inv = 1.f / (s_my + 1e-16f);
        __half2 o0 = __float22half2_rn(make_float2(acc[0] * inv, acc[1] * inv));
        __half2 o1 = __float22half2_rn(make_float2(acc[2] * inv, acc[3] * inv));
        __half2 o2 = __float22half2_rn(make_float2(acc[4] * inv, acc[5] * inv));
        __half2 o3 = __float22half2_rn(make_float2(acc[6] * inv, acc[7] * inv));
        uint4 o;
        o.x = *reinterpret_cast<uint32_t*>(&o0);
        o.y = *reinterpret_cast<uint32_t*>(&o1);
        o.z = *reinterpret_cast<uint32_t*>(&o2);
        o.w = *reinterpret_cast<uint32_t*>(&o3);
        *reinterpret_cast<uint4*>(&g_accum[(size_t)node * CH + chan]) = o;
    }
}

// ---------------- launch ----------------
extern "C" void kernel_launch(void* const* d_in, const int* in_sizes, int n_in,
                              void* d_out, int out_size)
{
    const float* x     = (const float*)d_in[0];
    const int*   ei    = (const int*)  d_in[1];
    const float* W     = (const float*)d_in[2];
    const float* att_s = (const float*)d_in[3];
    const float* att_d = (const float*)d_in[4];
    const float* lin_w = (const float*)d_in[5];
    const float* lin_b = (const float*)d_in[6];
    float* out = (float*)d_out;

    int N = in_sizes[0] / CH;    // 100000
    int E = in_sizes[1] / 2;     // 1600000

    void *p_h, *p_acc, *p_whi, *p_wlo, *p_lwhi, *p_lwlo;
    cudaGetSymbolAddress(&p_h, g_h);
    cudaGetSymbolAddress(&p_acc, g_accum);
    cudaGetSymbolAddress(&p_whi, g_whi);
    cudaGetSymbolAddress(&p_wlo, g_wlo);
    cudaGetSymbolAddress(&p_lwhi, g_lwhi);
    cudaGetSymbolAddress(&p_lwlo, g_lwlo);

    const int SMEM = 98304;
    cudaFuncSetAttribute(gemm_mma<0>, cudaFuncAttributeMaxDynamicSharedMemorySize, SMEM);
    cudaFuncSetAttribute(gemm_mma<1>, cudaFuncAttributeMaxDynamicSharedMemorySize, SMEM);

    int ntiles = (N + 63) / 64;
    int gemm_blocks = (ntiles < 296) ? ntiles : 296;   // persistent, 2/SM

    // fork: csr_build (side stream) || prep + gemm1 (main stream) — proven topology
    cudaStream_t s2;
    cudaStreamCreateWithFlags(&s2, cudaStreamNonBlocking);
    cudaEvent_t ev_fork, ev_join;
    cudaEventCreateWithFlags(&ev_fork, cudaEventDisableTiming);
    cudaEventCreateWithFlags(&ev_join, cudaEventDisableTiming);

    cudaEventRecord(ev_fork, 0);
    cudaStreamWaitEvent(s2, ev_fork, 0);
    csr_build<<<NBLK, CBS, 0, s2>>>(ei, E, N);                                  // 0
    cudaEventRecord(ev_join, s2);

    prep_w<true><<<64, 256>>>(W, (unsigned char*)p_whi, (unsigned char*)p_wlo); // 1
    prep_w<false><<<64, 256>>>(lin_w, (unsigned char*)p_lwhi, (unsigned char*)p_lwlo); // 2
    gemm_mma<0><<<gemm_blocks, 256, SMEM>>>(                                    // 3 <- profiled
        x, (const unsigned char*)p_whi, (const unsigned char*)p_wlo,
        att_s, att_d, p_h, N);

    cudaStreamWaitEvent(0, ev_join, 0);
    gather_kernel<<<(N * 32 + 255) / 256, 256>>>(N);                            // 4
    gemm_mma<1><<<gemm_blocks, 256, SMEM>>>(                                    // 5
        p_acc, (const unsigned char*)p_lwhi, (const unsigned char*)p_lwlo,
        lin_b, nullptr, out, N);
}

// round 17
// speedup vs baseline: 1.2128x; 1.0595x over previous
#include <cuda_runtime.h>
#include <cuda_bf16.h>
#include <cuda_fp16.h>
#include <cstdint>

#define N_NODES 100000
#define N_EDGES 1600000
#define CH 128          // IN_CH = HEADS*HID = OUT_CH = 128
#define HEADS 4
#define HID 32
#define NEG_SLOPE 0.2f
#define NBLK 148
#define CBS 1024
#define DUMMY N_NODES   // dummy src node: asrc=-1e30 -> x=0 exactly

// ---------------- scratch (static device globals; no allocation) ----------------
__device__ __half g_h[(size_t)(N_NODES + 1) * CH]; // x @ W, fp16 (+1 zeroed dummy row)
__device__ __half g_accum[(size_t)N_NODES * CH];   // normalized messages, fp16
__device__ float g_asrc[(size_t)(N_NODES + 1) * HEADS]; // pre-scaled by log2(e); +dummy
__device__ float g_adst[(size_t)N_NODES * HEADS];  // pre-scaled by log2(e)
__device__ int   g_deg[N_NODES];
__device__ int   g_off[N_NODES];
__device__ int   g_pos[N_EDGES];                   // per-edge slot within its dst list
__device__ int   g_srcs[N_EDGES];
__device__ int   g_bsum[NBLK];
__device__ unsigned g_c[8];                        // grid-barrier counters (zero-init)
// pre-swizzled fp16 hi/lo images of W^T and lin_w^T ([n][k] layout, 32KB each)
__device__ __align__(16) unsigned char g_whi[32768];
__device__ __align__(16) unsigned char g_wlo[32768];
__device__ __align__(16) unsigned char g_lwhi[32768];
__device__ __align__(16) unsigned char g_lwlo[32768];

#define LOG2E 1.4426950408889634f

// smem layout (bytes): A 16K | B_hi 32K | B_lo 32K
#define SM_BHI 16384
#define SM_BLO 49152
#define SMEM_TOT 81920

// ---------------- helpers ----------------
__device__ __forceinline__ uint32_t s2u(const void* p) {
    uint32_t a;
    asm("{ .reg .u64 t; cvta.to.shared.u64 t, %1; cvt.u32.u64 %0, t; }" : "=r"(a) : "l"(p));
    return a;
}

// swizzled byte offset inside a [rows][128 fp16] tile (256B rows, XOR-16B-chunk swizzle)
__device__ __forceinline__ uint32_t swz(int row, int col) {
    return (uint32_t)(row * 256 + ((((col >> 3) ^ (row & 7))) << 4) + (col & 7) * 2);
}

#define LDSM4(r, addr) \
    asm volatile("ldmatrix.sync.aligned.m8n8.x4.shared.b16 {%0,%1,%2,%3}, [%4];" \
        : "=r"((r)[0]), "=r"((r)[1]), "=r"((r)[2]), "=r"((r)[3]) : "r"(addr))

// fp16 inputs, fp32 accumulate
#define MMAF16(d, a, b0, b1) \
    asm volatile("mma.sync.aligned.m16n8k16.row.col.f32.f16.f16.f32 " \
        "{%0,%1,%2,%3}, {%4,%5,%6,%7}, {%8,%9}, {%0,%1,%2,%3};" \
        : "+f"((d)[0]), "+f"((d)[1]), "+f"((d)[2]), "+f"((d)[3]) \
        : "r"((a)[0]), "r"((a)[1]), "r"((a)[2]), "r"((a)[3]), "r"(b0), "r"(b1))

// fast 2^x and leaky-relu
__device__ __forceinline__ float ex2f(float x) {
    float r;
    asm("ex2.approx.f32 %0, %1;" : "=f"(r) : "f"(x));
    return r;
}
__device__ __forceinline__ float lrelu(float e) {
    return fmaf(fminf(e, 0.f), -(1.f - NEG_SLOPE), e);
}

// ---------------- software grid barrier ----------------
__device__ __forceinline__ void gbar(int ph) {
    __syncthreads();
    if (threadIdx.x == 0) {
        __threadfence();
        atomicAdd(&g_c[ph], 1u);
        while (*(volatile unsigned*)&g_c[ph] < (unsigned)NBLK) { __nanosleep(64); }
        __threadfence();
    }
    __syncthreads();
}

// ---------------- fused CSR build (pos-recording; atomic-free placement) ----------------
__global__ void __launch_bounds__(CBS, 1) csr_build(const int* __restrict__ ei, int E, int N)
{
    __shared__ int sm[CBS];
    const int b = blockIdx.x, t = threadIdx.x;
    const int gt = b * CBS + t;
    const int GS = NBLK * CBS;
    const int CHUNK = (N + NBLK - 1) / NBLK;
    const int base = b * CHUNK;

    for (int i = gt; i < N; i += GS) g_deg[i] = 0;
    gbar(0);

    for (int i = gt; i < E; i += GS) {
        int pos = atomicAdd(&g_deg[ei[E + i]], 1);
        g_pos[i] = pos;
    }
    gbar(1);

    int myv = 0;
    if (t < CHUNK && base + t < N) myv = __ldcg(&g_deg[base + t]);
    sm[t] = myv;
    __syncthreads();
#pragma unroll
    for (int d = 1; d < CBS; d <<= 1) {
        int v2 = (t >= d) ? sm[t - d] : 0;
        __syncthreads();
        sm[t] += v2;
        __syncthreads();
    }
    int incl = sm[t];
    if (t < CHUNK && base + t < N) g_off[base + t] = incl - myv;
    if (t == CBS - 1) g_bsum[b] = incl;
    gbar(2);

    if (b == 0) {
        int v = (t < NBLK) ? __ldcg(&g_bsum[t]) : 0;
        sm[t] = v;
        __syncthreads();
#pragma unroll
        for (int d = 1; d < CBS; d <<= 1) {
            int v2 = (t >= d) ? sm[t - d] : 0;
            __syncthreads();
            sm[t] += v2;
            __syncthreads();
        }
        if (t < NBLK) g_bsum[t] = sm[t] - v;
    }
    gbar(3);

    {
        int boff = __ldcg(&g_bsum[b]);
        if (t < CHUNK && base + t < N)
            g_off[base + t] += boff;
    }
    gbar(4);

    for (int i = gt; i < E; i += GS) {
        int dst = ei[E + i];
        g_srcs[__ldcg(&g_off[dst]) + g_pos[i]] = ei[i];
    }
    gbar(5);

    if (b == 0 && t < 8) g_c[t] = 0;
}

// ---------------- prep: one weight matrix -> fp16 hi/lo, swizzled ----------------
template<bool INIT_DUMMY>
__global__ void prep_w(const float* __restrict__ src,
                       unsigned char* __restrict__ dhi, unsigned char* __restrict__ dlo)
{
    int idx = blockIdx.x * blockDim.x + threadIdx.x;   // 16384
    int n = idx >> 7, k = idx & 127;
    float v = src[k * CH + n];
    __half h = __float2half_rn(v);
    __half l = __float2half_rn(v - __half2float(h));
    uint32_t o = swz(n, k);
    *reinterpret_cast<__half*>(dhi + o) = h;
    *reinterpret_cast<__half*>(dlo + o) = l;

    if (INIT_DUMMY && blockIdx.x == 0) {
        int t = threadIdx.x;
        if (t < 64)
            reinterpret_cast<uint32_t*>(&g_h[(size_t)DUMMY * CH])[t] = 0u;
        else if (t < 64 + HEADS)
            g_asrc[(size_t)DUMMY * HEADS + (t - 64)] = -1e30f;
    }
}

// ---------------- tensor-core GEMM (fp16 A single image, fp16-split B, 2 products) ----------------
// Warp tile 32 rows x 32 cols (2x4 warp grid): 6 LDSM4/kk, 16 MMA/kk.
// MODE 0: A = fp32 x (converted fp16);  C = g_h (fp16) + fused a_src/a_dst epilogue
// MODE 1: A = fp16 accum (copied raw);  C = out (fp32) with bias(v0) + ReLU
template<int MODE>
__global__ void __launch_bounds__(256, 2) gemm_mma(
    const void* __restrict__ Av,
    const unsigned char* __restrict__ Bhi_g, const unsigned char* __restrict__ Blo_g,
    const float* __restrict__ v0, const float* __restrict__ v1,
    void* __restrict__ Cv, int M)
{
    extern __shared__ __align__(16) unsigned char smem[];
    const uint32_t sb = s2u(smem);
    const int tid = threadIdx.x, lane = tid & 31, w = tid >> 5;

    // copy B hi/lo tiles once (32KB each)
    {
        const int4* bh = reinterpret_cast<const int4*>(Bhi_g);
        const int4* bl = reinterpret_cast<const int4*>(Blo_g);
        int4* dh = reinterpret_cast<int4*>(smem + SM_BHI);
        int4* dl = reinterpret_cast<int4*>(smem + SM_BLO);
#pragma unroll
        for (int u = 0; u < 8; ++u) {
            int f = tid + u * 256;
            dh[f] = bh[f];
            dl[f] = bl[f];
        }
    }

    const int wr = (w & 1) * 32;       // warp rows [wr, wr+32)
    const int wc = (w >> 1) * 32;      // warp cols [wc, wc+32)
    const int arow  = wr + (lane & 7) + ((lane >> 3) & 1) * 8;
    const int asel  = lane >> 4;
    const int arow7 = arow & 7;
    const int bg_row = (lane & 7) + ((lane >> 4) & 1) * 8;
    const int bsel   = (lane >> 3) & 1;
    const uint32_t brow_base = (uint32_t)(SM_BHI + (wc + bg_row) * 256);

    const int ntiles = (M + 63) / 64;
    for (int tile = blockIdx.x; tile < ntiles; tile += gridDim.x) {
        const int row0 = tile * 64;

        __syncthreads();   // protect A smem from previous iteration's readers

        if (MODE == 0) {
            // fp32 -> fp16, 8192 elems; thread handles 4 elems/iter x 8 iters
            const float* A = (const float*)Av;
#pragma unroll
            for (int u = 0; u < 8; ++u) {
                int f = tid + u * 256;
                int r = f >> 5;
                int c = (f & 31) * 4;
                float4 v = make_float4(0.f, 0.f, 0.f, 0.f);
                if (row0 + r < M)
                    v = *reinterpret_cast<const float4*>(&A[(size_t)(row0 + r) * CH + c]);
                __half2 p01 = __floats2half2_rn(v.x, v.y);
                __half2 p23 = __floats2half2_rn(v.z, v.w);
                uint2 up;
                up.x = *reinterpret_cast<uint32_t*>(&p01);
                up.y = *reinterpret_cast<uint32_t*>(&p23);
                *reinterpret_cast<uint2*>(smem + swz(r, c)) = up;
            }
        } else {
            // fp16 raw copy, 1024 uint4
            const __half* A = (const __half*)Av;
#pragma unroll
            for (int u = 0; u < 4; ++u) {
                int f = tid + u * 256;
                int r = f >> 4;
                int c = (f & 15) * 8;
                uint4 hv = make_uint4(0u, 0u, 0u, 0u);
                if (row0 + r < M)
                    hv = *reinterpret_cast<const uint4*>(&A[(size_t)(row0 + r) * CH + c]);
                *reinterpret_cast<uint4*>(smem + swz(r, c)) = hv;
            }
        }
        __syncthreads();

        float acc[2][4][4];   // [m16 tile][n8 tile][frag]
#pragma unroll
        for (int p = 0; p < 2; ++p)
#pragma unroll
            for (int j = 0; j < 4; ++j)
#pragma unroll
                for (int q = 0; q < 4; ++q) acc[p][j][q] = 0.f;

#pragma unroll
        for (int kk = 0; kk < 8; ++kk) {
            const uint32_t kxor = (uint32_t)(((kk * 2 + asel) ^ arow7) << 4);
            const uint32_t aaddr = sb + (uint32_t)(arow * 256) + kxor;
            uint32_t a[8];
            LDSM4(&a[0], aaddr);
            LDSM4(&a[4], aaddr + 4096);              // +16 rows, same xor

            const uint32_t bxor = (uint32_t)(((kk * 2 + bsel) ^ (bg_row & 7)) << 4);
            const uint32_t baddr = sb + brow_base + bxor;
            uint32_t b_hi[8], b_lo[8];
            LDSM4(&b_hi[0], baddr);
            LDSM4(&b_hi[4], baddr + 4096);           // +16 cols
            LDSM4(&b_lo[0], baddr + 32768);
            LDSM4(&b_lo[4], baddr + 32768 + 4096);

#pragma unroll
            for (int p = 0; p < 2; ++p)
#pragma unroll
                for (int j = 0; j < 4; ++j) {
                    int i0 = (j >> 1) * 4 + (j & 1) * 2;
                    MMAF16(acc[p][j], &a[p * 4], b_hi[i0], b_hi[i0 + 1]);
                }
#pragma unroll
            for (int p = 0; p < 2; ++p)
#pragma unroll
                for (int j = 0; j < 4; ++j) {
                    int i0 = (j >> 1) * 4 + (j & 1) * 2;
                    MMAF16(acc[p][j], &a[p * 4], b_lo[i0], b_lo[i0 + 1]);
                }
        }

#pragma unroll
        for (int p = 0; p < 2; ++p) {
            const int r_g = row0 + wr + p * 16 + (lane >> 2);
#pragma unroll
            for (int j = 0; j < 4; ++j) {
                int n0 = wc + j * 8 + (lane & 3) * 2;
                if (MODE == 1) {
                    float* C = (float*)Cv;
                    float b0 = __ldg(&v0[n0]), b1 = __ldg(&v0[n0 + 1]);
                    float2 o0, o1;
                    o0.x = fmaxf(acc[p][j][0] + b0, 0.f); o0.y = fmaxf(acc[p][j][1] + b1, 0.f);
                    o1.x = fmaxf(acc[p][j][2] + b0, 0.f); o1.y = fmaxf(acc[p][j][3] + b1, 0.f);
                    if (r_g < M)
                        *reinterpret_cast<float2*>(&C[(size_t)r_g * CH + n0]) = o0;
                    if (r_g + 8 < M)
                        *reinterpret_cast<float2*>(&C[(size_t)(r_g + 8) * CH + n0]) = o1;
                } else {
                    __half* C = (__half*)Cv;
                    __half2 o0 = __float22half2_rn(make_float2(acc[p][j][0], acc[p][j][1]));
                    __half2 o1 = __float22half2_rn(make_float2(acc[p][j][2], acc[p][j][3]));
                    if (r_g < M)
                        *reinterpret_cast<__half2*>(&C[(size_t)r_g * CH + n0]) = o0;
                    if (r_g + 8 < M)
                        *reinterpret_cast<__half2*>(&C[(size_t)(r_g + 8) * CH + n0]) = o1;
                }
            }
        }

        if (MODE == 0) {
            // fused att projections: this warp covers exactly one head (wc/32)
            float ps[2][2] = {{0.f, 0.f}, {0.f, 0.f}};
            float pd[2][2] = {{0.f, 0.f}, {0.f, 0.f}};
#pragma unroll
            for (int p = 0; p < 2; ++p)
#pragma unroll
                for (int j = 0; j < 4; ++j) {
                    int n0 = wc + j * 8 + (lane & 3) * 2;
                    float s0 = __ldg(&v0[n0]), s1 = __ldg(&v0[n0 + 1]);
                    float d0 = __ldg(&v1[n0]), d1 = __ldg(&v1[n0 + 1]);
                    ps[p][0] += acc[p][j][0] * s0 + acc[p][j][1] * s1;
                    ps[p][1] += acc[p][j][2] * s0 + acc[p][j][3] * s1;
                    pd[p][0] += acc[p][j][0] * d0 + acc[p][j][1] * d1;
                    pd[p][1] += acc[p][j][2] * d0 + acc[p][j][3] * d1;
                }
#pragma unroll
            for (int o = 1; o < 4; o <<= 1) {
#pragma unroll
                for (int p = 0; p < 2; ++p)
#pragma unroll
                    for (int rh = 0; rh < 2; ++rh) {
                        ps[p][rh] += __shfl_xor_sync(0xFFFFFFFFu, ps[p][rh], o);
                        pd[p][rh] += __shfl_xor_sync(0xFFFFFFFFu, pd[p][rh], o);
                    }
            }
            if ((lane & 3) == 0) {
                int h0 = wc >> 5;
#pragma unroll
                for (int p = 0; p < 2; ++p) {
                    int r_g = row0 + wr + p * 16 + (lane >> 2);
                    if (r_g < M) {
                        g_asrc[(size_t)r_g * HEADS + h0] = ps[p][0] * LOG2E;
                        g_adst[(size_t)r_g * HEADS + h0] = pd[p][0] * LOG2E;
                    }
                    if (r_g + 8 < M) {
                        g_asrc[(size_t)(r_g + 8) * HEADS + h0] = ps[p][1] * LOG2E;
                        g_adst[(size_t)(r_g + 8) * HEADS + h0] = pd[p][1] * LOG2E;
                    }
                }
            }
        }
    }
}

// ---------------- gather v5: fp16 h, 2 edges/step, 8 ch/lane, guard-free via dummy ----------------
__global__ void __launch_bounds__(256) gather_kernel(int N)
{
    int node = (blockIdx.x * blockDim.x + threadIdx.x) >> 5;
    if (node >= N) return;
    const int lane = threadIdx.x & 31;
    const int sub  = lane & 15;        // channel group
    const int half = lane >> 4;        // edge parity within a step pair
    const int head = sub >> 2;
    const int chan = sub * 8;

    const int off = g_off[node];
    const int deg = g_deg[node];

    const float ad_my = __ldg(&g_adst[(size_t)node * HEADS + head]);

    float acc[8];
#pragma unroll
    for (int c = 0; c < 8; ++c) acc[c] = 0.f;
    float s_my = 0.f;

    for (int base = 0; base < deg; base += 32) {
        int idx = DUMMY;                       // out-of-range lanes -> x = 0 exactly
        if (base + lane < deg) idx = g_srcs[off + base + lane];
        int cnt = min(32, deg - base);
        for (int j = 0; j < cnt; j += 4) {
            int s0 = __shfl_sync(0xFFFFFFFFu, idx, j + half);
            int s1 = __shfl_sync(0xFFFFFFFFu, idx, j + 2 + half);
            float as0 = __ldg(&g_asrc[(size_t)s0 * HEADS + head]);
            float as1 = __ldg(&g_asrc[(size_t)s1 * HEADS + head]);
            uint4 u0 = *reinterpret_cast<const uint4*>(&g_h[(size_t)s0 * CH + chan]);
            uint4 u1 = *reinterpret_cast<const uint4*>(&g_h[(size_t)s1 * CH + chan]);

            float x0 = ex2f(lrelu(as0 + ad_my));
            float x1 = ex2f(lrelu(as1 + ad_my));

            float2 f;
            f = __half22float2(*reinterpret_cast<__half2*>(&u0.x));
            acc[0] = fmaf(x0, f.x, acc[0]); acc[1] = fmaf(x0, f.y, acc[1]);
            f = __half22float2(*reinterpret_cast<__half2*>(&u0.y));
            acc[2] = fmaf(x0, f.x, acc[2]); acc[3] = fmaf(x0, f.y, acc[3]);
            f = __half22float2(*reinterpret_cast<__half2*>(&u0.z));
            acc[4] = fmaf(x0, f.x, acc[4]); acc[5] = fmaf(x0, f.y, acc[5]);
            f = __half22float2(*reinterpret_cast<__half2*>(&u0.w));
            acc[6] = fmaf(x0, f.x, acc[6]); acc[7] = fmaf(x0, f.y, acc[7]);

            f = __half22float2(*reinterpret_cast<__half2*>(&u1.x));
            acc[0] = fmaf(x1, f.x, acc[0]); acc[1] = fmaf(x1, f.y, acc[1]);
            f = __half22float2(*reinterpret_cast<__half2*>(&u1.y));
            acc[2] = fmaf(x1, f.x, acc[2]); acc[3] = fmaf(x1, f.y, acc[3]);
            f = __half22float2(*reinterpret_cast<__half2*>(&u1.z));
            acc[4] = fmaf(x1, f.x, acc[4]); acc[5] = fmaf(x1, f.y, acc[5]);
            f = __half22float2(*reinterpret_cast<__half2*>(&u1.w));
            acc[6] = fmaf(x1, f.x, acc[6]); acc[7] = fmaf(x1, f.y, acc[7]);

            s_my += x0 + x1;
        }
    }

#pragma unroll
    for (int c = 0; c < 8; ++c)
        acc[c] += __shfl_xor_sync(0xFFFFFFFFu, acc[c], 16);
    s_my += __shfl_xor_sync(0xFFFFFFFFu, s_my, 16);

    if (half == 0) {
        float inv = 1.f / (s_my + 1e-16f);
        __half2 o0 = __float22half2_rn(make_float2(acc[0] * inv, acc[1] * inv));
        __half2 o1 = __float22half2_rn(make_float2(acc[2] * inv, acc[3] * inv));
        __half2 o2 = __float22half2_rn(make_float2(acc[4] * inv, acc[5] * inv));
        __half2 o3 = __float22half2_rn(make_float2(acc[6] * inv, acc[7] * inv));
        uint4 o;
        o.x = *reinterpret_cast<uint32_t*>(&o0);
        o.y = *reinterpret_cast<uint32_t*>(&o1);
        o.z = *reinterpret_cast<uint32_t*>(&o2);
        o.w = *reinterpret_cast<uint32_t*>(&o3);
        *reinterpret_cast<uint4*>(&g_accum[(size_t)node * CH + chan]) = o;
    }
}

// ---------------- launch ----------------
extern "C" void kernel_launch(void* const* d_in, const int* in_sizes, int n_in,
                              void* d_out, int out_size)
{
    const float* x     = (const float*)d_in[0];
    const int*   ei    = (const int*)  d_in[1];
    const float* W     = (const float*)d_in[2];
    const float* att_s = (const float*)d_in[3];
    const float* att_d = (const float*)d_in[4];
    const float* lin_w = (const float*)d_in[5];
    const float* lin_b = (const float*)d_in[6];
    float* out = (float*)d_out;

    int N = in_sizes[0] / CH;    // 100000
    int E = in_sizes[1] / 2;     // 1600000

    void *p_h, *p_acc, *p_whi, *p_wlo, *p_lwhi, *p_lwlo;
    cudaGetSymbolAddress(&p_h, g_h);
    cudaGetSymbolAddress(&p_acc, g_accum);
    cudaGetSymbolAddress(&p_whi, g_whi);
    cudaGetSymbolAddress(&p_wlo, g_wlo);
    cudaGetSymbolAddress(&p_lwhi, g_lwhi);
    cudaGetSymbolAddress(&p_lwlo, g_lwlo);

    cudaFuncSetAttribute(gemm_mma<0>, cudaFuncAttributeMaxDynamicSharedMemorySize, SMEM_TOT);
    cudaFuncSetAttribute(gemm_mma<1>, cudaFuncAttributeMaxDynamicSharedMemorySize, SMEM_TOT);

    int ntiles = (N + 63) / 64;
    int gemm_blocks = (ntiles < 296) ? ntiles : 296;   // persistent, 2/SM

    // fork: csr_build (side stream) || prep + gemm1 (main stream) — proven topology
    cudaStream_t s2;
    cudaStreamCreateWithFlags(&s2, cudaStreamNonBlocking);
    cudaEvent_t ev_fork, ev_join;
    cudaEventCreateWithFlags(&ev_fork, cudaEventDisableTiming);
    cudaEventCreateWithFlags(&ev_join, cudaEventDisableTiming);

    cudaEventRecord(ev_fork, 0);
    cudaStreamWaitEvent(s2, ev_fork, 0);
    csr_build<<<NBLK, CBS, 0, s2>>>(ei, E, N);                                  // 0
    cudaEventRecord(ev_join, s2);

    prep_w<true><<<64, 256>>>(W, (unsigned char*)p_whi, (unsigned char*)p_wlo); // 1
    prep_w<false><<<64, 256>>>(lin_w, (unsigned char*)p_lwhi, (unsigned char*)p_lwlo); // 2
    gemm_mma<0><<<gemm_blocks, 256, SMEM_TOT>>>(                                // 3 <- profiled
        x, (const unsigned char*)p_whi, (const unsigned char*)p_wlo,
        att_s, att_d, p_h, N);

    cudaStreamWaitEvent(0, ev_join, 0);
    gather_kernel<<<(N * 32 + 255) / 256, 256>>>(N);                            // 4
    gemm_mma<1><<<gemm_blocks, 256, SMEM_TOT>>>(                                // 5
        p_acc, (const unsigned char*)p_lwhi, (const unsigned char*)p_lwlo,
        lin_b, nullptr, out, N);
}